// round 12
// baseline (speedup 1.0000x reference)
#include <cuda_runtime.h>
#include <math.h>

#define B_   4
#define SEQ_ 12
#define NN   1024
#define SL   3
#define SG   4
#define HID  64
#define FFD  2048
#define DKk  32
#define LAY  2
#define TOK  (B_*NN*SG)   /* 16384 per stream */
#define GRP  (B_*SG)      /* 16 per stream */

// ---------------- scratch (static device memory) ----------------
__device__ float d_Z[2*TOK*HID];          // [s][b][n][seg][h]
__device__ float d_Qb[2*GRP*NN*DKk];
__device__ float d_Kb[2*GRP*NN*DKk];
__device__ float d_Vb[2*GRP*NN*HID];
__device__ float d_ENC[B_*NN*2*HID];
__device__ float d_Q2[B_*NN*DKk];
__device__ float d_K2[B_*NN*DKk];
__device__ float d_V2[B_*NN*HID];

// ---------------- tf32 helpers ----------------
__device__ __forceinline__ unsigned f2tf32(float x) {
    unsigned r;
    asm("cvt.rna.tf32.f32 %0, %1;" : "=r"(r) : "f"(x));
    return r;
}
__device__ __forceinline__ void mma_tf32(float* c,
        unsigned a0, unsigned a1, unsigned a2, unsigned a3,
        unsigned b0, unsigned b1) {
    asm volatile("mma.sync.aligned.m16n8k8.row.col.f32.tf32.tf32.f32 "
        "{%0,%1,%2,%3}, {%4,%5,%6,%7}, {%8,%9}, {%0,%1,%2,%3};"
        : "+f"(c[0]), "+f"(c[1]), "+f"(c[2]), "+f"(c[3])
        : "r"(a0), "r"(a1), "r"(a2), "r"(a3), "r"(b0), "r"(b1));
}

// ---------------- patch embedding + positional encoding (both streams) ----------------
__global__ __launch_bounds__(256) void patch_kernel(const float* __restrict__ traffic,
                                                    const float* __restrict__ user,
                                                    const float* __restrict__ pw,
                                                    const float* __restrict__ pb,
                                                    float* __restrict__ Z) {
    int blk = blockIdx.x;                // 0..8191
    int s   = blk >> 12;
    int bn  = blk & 4095;
    int b   = bn >> 10, n = bn & 1023;
    const float* x = s ? user : traffic;
    const float* pws = pw + s*HID*SL;
    const float* pbs = pb + s*HID;
    int t   = threadIdx.x;
    int seg = t >> 6, h = t & 63;
    float acc = pbs[h];
#pragma unroll
    for (int l = 0; l < SL; l++)
        acc += pws[h*SL + l] * x[(b*SEQ_ + seg*SL + l)*NN + n];
    int he = h & ~1;
    float dv = expf(-(float)he * (9.210340371976184f / (float)HID));
    float ang = (float)seg * dv;
    acc += (h & 1) ? cosf(ang) : sinf(ang);
    Z[(size_t)(s*TOK + bn*SG + seg)*HID + h] = acc;
}

// ---------------- temporal encoder: MHA + residual + LN1; 64 tokens / block ----------------
// GEMMs (QKV, out-proj) on tf32 tensor cores; 4x4 attention core scalar.
#define MHA_SMEM_FLOATS (4352 + 4352 + 12800 + 2048 + 4352)
__global__ __launch_bounds__(256) void mha_kernel(float* __restrict__ Z,
        const float* __restrict__ mw_, const float* __restrict__ mb_,
        const float* __restrict__ ow_, const float* __restrict__ ob_,
        const float* __restrict__ g1_, const float* __restrict__ b1_, int layer) {
    extern __shared__ float sm[];
    float (*xs)[68]  = (float(*)[68])sm;
    float (*wb)[68]  = (float(*)[68])(sm + 4352);
    float (*qkv)[200]= (float(*)[200])(sm + 8704);
    float *ps        = sm + 21504;
    float (*os)[68]  = (float(*)[68])(sm + 23552);

    int tid = threadIdx.x;
    int s  = blockIdx.x >> 8;                 // 512 blocks, 256 per stream
    int o  = s*LAY + layer;
    const float* mw = mw_ + (size_t)o*192*64;
    const float* mb = mb_ + (size_t)o*192;
    const float* ow = ow_ + (size_t)o*64*64;
    const float* ob = ob_ + (size_t)o*64;
    const float* g1 = g1_ + (size_t)o*64;
    const float* b1 = b1_ + (size_t)o*64;
    size_t t0 = (size_t)blockIdx.x * 64;
    float* zb = Z + t0 * HID;

    int wid = tid >> 5, lane = tid & 31;
    int lr = lane >> 2, lc = lane & 3;
    int wm = wid >> 2, wn = wid & 3;          // warp grid 2(m) x 4(n)
    int mb2 = wm*32, nb = wn*16;

    for (int idx = tid; idx < 64*16; idx += 256) {
        int r = idx >> 4, c4 = idx & 15;
        *(float4*)&xs[r][4*c4] = *(const float4*)&zb[(size_t)r*64 + 4*c4];
    }

    // ---- QKV = X @ W^T + b  (3 chunks of 64 cols), tf32 mma ----
    for (int cc = 0; cc < 3; cc++) {
        __syncthreads();
        for (int idx = tid; idx < 64*16; idx += 256) {
            int r = idx >> 4, c4 = idx & 15;
            float4 v = *(const float4*)&mw[(size_t)(cc*64 + r)*64 + 4*c4];
            wb[r][4*c4+0] = __uint_as_float(f2tf32(v.x));
            wb[r][4*c4+1] = __uint_as_float(f2tf32(v.y));
            wb[r][4*c4+2] = __uint_as_float(f2tf32(v.z));
            wb[r][4*c4+3] = __uint_as_float(f2tf32(v.w));
        }
        __syncthreads();
        float acc[2][2][4];
#pragma unroll
        for (int j = 0; j < 2; j++) {
            int c = nb + 8*j + 2*lc;
            float bv0 = mb[cc*64 + c], bv1 = mb[cc*64 + c + 1];
#pragma unroll
            for (int t = 0; t < 2; t++) {
                acc[t][j][0] = bv0; acc[t][j][1] = bv1;
                acc[t][j][2] = bv0; acc[t][j][3] = bv1;
            }
        }
#pragma unroll
        for (int k0 = 0; k0 < 64; k0 += 8) {
            unsigned a[2][4];
#pragma unroll
            for (int t = 0; t < 2; t++) {
                int r = mb2 + 16*t + lr;
                a[t][0] = f2tf32(xs[r][k0+lc]);
                a[t][1] = f2tf32(xs[r+8][k0+lc]);
                a[t][2] = f2tf32(xs[r][k0+lc+4]);
                a[t][3] = f2tf32(xs[r+8][k0+lc+4]);
            }
#pragma unroll
            for (int j = 0; j < 2; j++) {
                unsigned b0 = __float_as_uint(wb[nb+8*j+lr][k0+lc]);
                unsigned bq = __float_as_uint(wb[nb+8*j+lr][k0+lc+4]);
#pragma unroll
                for (int t = 0; t < 2; t++)
                    mma_tf32(acc[t][j], a[t][0], a[t][1], a[t][2], a[t][3], b0, bq);
            }
        }
#pragma unroll
        for (int t = 0; t < 2; t++)
#pragma unroll
            for (int j = 0; j < 2; j++) {
                int r = mb2 + 16*t + lr, c = cc*64 + nb + 8*j + 2*lc;
                qkv[r][c]     = acc[t][j][0];
                qkv[r][c+1]   = acc[t][j][1];
                qkv[r+8][c]   = acc[t][j][2];
                qkv[r+8][c+1] = acc[t][j][3];
            }
    }
    __syncthreads();

    // ---- scores + softmax (scalar; tiny) ----
    for (int T = tid; T < 512; T += 256) {
        int g = T >> 5, h = (T >> 2) & 7, i = T & 3;
        const float* q = &qkv[g*4 + i][h*8];
        float sc[4];
#pragma unroll
        for (int j = 0; j < 4; j++) {
            const float* kk = &qkv[g*4 + j][64 + h*8];
            float a = 0.f;
#pragma unroll
            for (int d = 0; d < 8; d++) a += q[d] * kk[d];
            sc[j] = a * 0.3535533905932738f;
        }
        float m = fmaxf(fmaxf(sc[0], sc[1]), fmaxf(sc[2], sc[3]));
        float e0 = __expf(sc[0]-m), e1 = __expf(sc[1]-m), e2 = __expf(sc[2]-m), e3 = __expf(sc[3]-m);
        float inv = 1.f / (e0+e1+e2+e3);
        ps[T*4+0] = e0*inv; ps[T*4+1] = e1*inv; ps[T*4+2] = e2*inv; ps[T*4+3] = e3*inv;
    }
    __syncthreads();

    // ---- O = att @ V (scalar; tiny) ----
    {
        int ty = tid >> 4, tx = tid & 15;
#pragma unroll
        for (int i = 0; i < 4; i++) {
            int r = 4*ty + i;
            int g = r >> 2, ii = r & 3;
#pragma unroll
            for (int j = 0; j < 4; j++) {
                int c = tx + 16*j;
                int h = c >> 3;
                const float* a = ps + (((g*8 + h)*4) + ii)*4;
                os[r][c] = a[0]*qkv[g*4+0][128+c] + a[1]*qkv[g*4+1][128+c]
                         + a[2]*qkv[g*4+2][128+c] + a[3]*qkv[g*4+3][128+c];
            }
        }
    }
    __syncthreads();

    // ---- out proj + residual, tf32 mma ----
    for (int idx = tid; idx < 64*16; idx += 256) {
        int r = idx >> 4, c4 = idx & 15;
        float4 v = *(const float4*)&ow[(size_t)r*64 + 4*c4];
        wb[r][4*c4+0] = __uint_as_float(f2tf32(v.x));
        wb[r][4*c4+1] = __uint_as_float(f2tf32(v.y));
        wb[r][4*c4+2] = __uint_as_float(f2tf32(v.z));
        wb[r][4*c4+3] = __uint_as_float(f2tf32(v.w));
    }
    __syncthreads();
    {
        float acc[2][2][4];
#pragma unroll
        for (int j = 0; j < 2; j++) {
            int c = nb + 8*j + 2*lc;
            float bv0 = ob[c], bv1 = ob[c+1];
#pragma unroll
            for (int t = 0; t < 2; t++) {
                acc[t][j][0] = bv0; acc[t][j][1] = bv1;
                acc[t][j][2] = bv0; acc[t][j][3] = bv1;
            }
        }
#pragma unroll
        for (int k0 = 0; k0 < 64; k0 += 8) {
            unsigned a[2][4];
#pragma unroll
            for (int t = 0; t < 2; t++) {
                int r = mb2 + 16*t + lr;
                a[t][0] = f2tf32(os[r][k0+lc]);
                a[t][1] = f2tf32(os[r+8][k0+lc]);
                a[t][2] = f2tf32(os[r][k0+lc+4]);
                a[t][3] = f2tf32(os[r+8][k0+lc+4]);
            }
#pragma unroll
            for (int j = 0; j < 2; j++) {
                unsigned b0 = __float_as_uint(wb[nb+8*j+lr][k0+lc]);
                unsigned bq = __float_as_uint(wb[nb+8*j+lr][k0+lc+4]);
#pragma unroll
                for (int t = 0; t < 2; t++)
                    mma_tf32(acc[t][j], a[t][0], a[t][1], a[t][2], a[t][3], b0, bq);
            }
        }
        __syncthreads();
#pragma unroll
        for (int t = 0; t < 2; t++)
#pragma unroll
            for (int j = 0; j < 2; j++) {
                int r = mb2 + 16*t + lr, c = nb + 8*j + 2*lc;
                xs[r][c]     += acc[t][j][0];
                xs[r][c+1]   += acc[t][j][1];
                xs[r+8][c]   += acc[t][j][2];
                xs[r+8][c+1] += acc[t][j][3];
            }
    }
    __syncthreads();
    // ---- LN ----
    int w = tid >> 5, lane2 = tid & 31;
#pragma unroll
    for (int rr = 0; rr < 8; rr++) {
        int r = w*8 + rr;
        float v0 = xs[r][lane2], v1 = xs[r][lane2+32];
        float ssum = v0 + v1, q = v0*v0 + v1*v1;
#pragma unroll
        for (int off = 16; off; off >>= 1) { ssum += __shfl_xor_sync(0xffffffffu, ssum, off); q += __shfl_xor_sync(0xffffffffu, q, off); }
        float mean = ssum * (1.f/64.f);
        float var  = q * (1.f/64.f) - mean*mean;
        float rstd = rsqrtf(var + 1e-5f);
        zb[(size_t)r*64 + lane2]      = (v0 - mean)*rstd*g1[lane2]    + b1[lane2];
        zb[(size_t)r*64 + lane2 + 32] = (v1 - mean)*rstd*g1[lane2+32] + b1[lane2+32];
    }
}

// ---------------- fused FF + residual + LN: tf32 tensor cores, 128 tokens/block ----------------
// FF chunk 64 -> 104 KB smem -> 2 blocks/SM (wave fill + cross-block latency hiding)
// smem: xs[128][68] fp32 | hs[128][68] tf32 | w1s[64][68] tf32 | w2s[64][68] tf32
#define FF_SMEM_FLOATS (8704 + 8704 + 4352 + 4352)
__global__ __launch_bounds__(256) void ff_ln_kernel(float* __restrict__ Z,
        const float* __restrict__ w1_, const float* __restrict__ b1_,
        const float* __restrict__ w2_, const float* __restrict__ b2_,
        const float* __restrict__ g_, const float* __restrict__ bb_, int layer) {
    extern __shared__ float sm[];
    float (*xs)[68]  = (float(*)[68])sm;
    float (*hs)[68]  = (float(*)[68])(sm + 8704);
    float (*w1s)[68] = (float(*)[68])(sm + 17408);
    float (*w2s)[68] = (float(*)[68])(sm + 21760);

    int tid = threadIdx.x;
    int s   = blockIdx.x >> 7;           // 256 blocks, 128 per stream
    int o   = s*LAY + layer;
    const float* w1 = w1_ + (size_t)o*FFD*64;
    const float* b1 = b1_ + (size_t)o*FFD;
    const float* w2 = w2_ + (size_t)o*64*FFD;
    const float* b2 = b2_ + (size_t)o*64;
    const float* g  = g_  + (size_t)o*64;
    const float* bb = bb_ + (size_t)o*64;
    size_t t0 = (size_t)blockIdx.x * 128;

    int wid  = tid >> 5, lane = tid & 31;
    int lr = lane >> 2, lc = lane & 3;           // fragment row/col
    int wm = wid >> 2, wn = wid & 3;             // warp grid 2 x 4
    int mb = wm*64, nbh = wn*16, nbo = wn*16;

    for (int idx = tid; idx < 128*16; idx += 256) {
        int r = idx >> 4, c4 = idx & 15;
        *(float4*)&xs[r][4*c4] = *(const float4*)&Z[(t0 + r)*64 + 4*c4];
    }

    float oacc[4][2][4];
#pragma unroll
    for (int t = 0; t < 4; t++)
#pragma unroll
        for (int j = 0; j < 2; j++)
#pragma unroll
            for (int q = 0; q < 4; q++) oacc[t][j][q] = 0.f;

    for (int fc = 0; fc < FFD; fc += 64) {
        __syncthreads();
        // stage weights, pre-rounded to tf32
        for (int idx = tid; idx < 64*16; idx += 256) {
            int r = idx >> 4, c4 = idx & 15;
            float4 v = *(const float4*)&w1[(size_t)(fc+r)*64 + 4*c4];
            w1s[r][4*c4+0] = __uint_as_float(f2tf32(v.x));
            w1s[r][4*c4+1] = __uint_as_float(f2tf32(v.y));
            w1s[r][4*c4+2] = __uint_as_float(f2tf32(v.z));
            w1s[r][4*c4+3] = __uint_as_float(f2tf32(v.w));
        }
        for (int idx = tid; idx < 64*16; idx += 256) {
            int r = idx >> 4, c4 = idx & 15;
            float4 v = *(const float4*)&w2[(size_t)r*FFD + fc + 4*c4];
            w2s[r][4*c4+0] = __uint_as_float(f2tf32(v.x));
            w2s[r][4*c4+1] = __uint_as_float(f2tf32(v.y));
            w2s[r][4*c4+2] = __uint_as_float(f2tf32(v.z));
            w2s[r][4*c4+3] = __uint_as_float(f2tf32(v.w));
        }
        __syncthreads();

        // ---- H[128][64] = relu(X @ W1c^T + b1c), tf32 mma ----
        float hacc[4][2][4];
#pragma unroll
        for (int t = 0; t < 4; t++)
#pragma unroll
            for (int j = 0; j < 2; j++)
#pragma unroll
                for (int q = 0; q < 4; q++) hacc[t][j][q] = 0.f;

#pragma unroll
        for (int k0 = 0; k0 < 64; k0 += 8) {
            unsigned a[4][4];
#pragma unroll
            for (int t = 0; t < 4; t++) {
                int r = mb + 16*t + lr;
                a[t][0] = f2tf32(xs[r][k0+lc]);
                a[t][1] = f2tf32(xs[r+8][k0+lc]);
                a[t][2] = f2tf32(xs[r][k0+lc+4]);
                a[t][3] = f2tf32(xs[r+8][k0+lc+4]);
            }
#pragma unroll
            for (int j = 0; j < 2; j++) {
                unsigned b0 = __float_as_uint(w1s[nbh+8*j+lr][k0+lc]);
                unsigned bq = __float_as_uint(w1s[nbh+8*j+lr][k0+lc+4]);
#pragma unroll
                for (int t = 0; t < 4; t++)
                    mma_tf32(hacc[t][j], a[t][0], a[t][1], a[t][2], a[t][3], b0, bq);
            }
        }
#pragma unroll
        for (int j = 0; j < 2; j++) {
            int c = nbh + 8*j + 2*lc;
            float bv0 = b1[fc + c], bv1 = b1[fc + c + 1];
#pragma unroll
            for (int t = 0; t < 4; t++) {
                int r = mb + 16*t + lr;
                hs[r][c]     = __uint_as_float(f2tf32(fmaxf(hacc[t][j][0] + bv0, 0.f)));
                hs[r][c+1]   = __uint_as_float(f2tf32(fmaxf(hacc[t][j][1] + bv1, 0.f)));
                hs[r+8][c]   = __uint_as_float(f2tf32(fmaxf(hacc[t][j][2] + bv0, 0.f)));
                hs[r+8][c+1] = __uint_as_float(f2tf32(fmaxf(hacc[t][j][3] + bv1, 0.f)));
            }
        }
        __syncthreads();

        // ---- O[128][64] += H @ W2c^T, tf32 mma ----
#pragma unroll
        for (int k0 = 0; k0 < 64; k0 += 8) {
            unsigned a[4][4];
#pragma unroll
            for (int t = 0; t < 4; t++) {
                int r = mb + 16*t + lr;
                a[t][0] = __float_as_uint(hs[r][k0+lc]);
                a[t][1] = __float_as_uint(hs[r+8][k0+lc]);
                a[t][2] = __float_as_uint(hs[r][k0+lc+4]);
                a[t][3] = __float_as_uint(hs[r+8][k0+lc+4]);
            }
#pragma unroll
            for (int j = 0; j < 2; j++) {
                unsigned b0 = __float_as_uint(w2s[nbo+8*j+lr][k0+lc]);
                unsigned bq = __float_as_uint(w2s[nbo+8*j+lr][k0+lc+4]);
#pragma unroll
                for (int t = 0; t < 4; t++)
                    mma_tf32(oacc[t][j], a[t][0], a[t][1], a[t][2], a[t][3], b0, bq);
            }
        }
    }
    __syncthreads();
#pragma unroll
    for (int j = 0; j < 2; j++) {
        int c = nbo + 8*j + 2*lc;
        float bv0 = b2[c], bv1 = b2[c+1];
#pragma unroll
        for (int t = 0; t < 4; t++) {
            int r = mb + 16*t + lr;
            xs[r][c]     += oacc[t][j][0] + bv0;
            xs[r][c+1]   += oacc[t][j][1] + bv1;
            xs[r+8][c]   += oacc[t][j][2] + bv0;
            xs[r+8][c+1] += oacc[t][j][3] + bv1;
        }
    }
    __syncthreads();
    int w = tid >> 5, lane2 = tid & 31;
#pragma unroll
    for (int rr = 0; rr < 16; rr++) {
        int r = w*16 + rr;
        float v0 = xs[r][lane2], v1 = xs[r][lane2+32];
        float ssum = v0 + v1, q = v0*v0 + v1*v1;
#pragma unroll
        for (int off = 16; off; off >>= 1) { ssum += __shfl_xor_sync(0xffffffffu, ssum, off); q += __shfl_xor_sync(0xffffffffu, q, off); }
        float mean = ssum * (1.f/64.f);
        float var  = q * (1.f/64.f) - mean*mean;
        float rstd = rsqrtf(var + 1e-5f);
        Z[(t0+r)*64 + lane2]      = (v0 - mean)*rstd*g[lane2]    + bb[lane2];
        Z[(t0+r)*64 + lane2 + 32] = (v1 - mean)*rstd*g[lane2+32] + bb[lane2+32];
    }
}

// ---------------- graph-attention QKV projection: tf32 mma, 64 rows/block ----------------
__global__ __launch_bounds__(256) void ga_qkv_kernel(const float* __restrict__ Z,
        const float* __restrict__ wq_, const float* __restrict__ wk_, const float* __restrict__ wv_,
        float* __restrict__ Q, float* __restrict__ K, float* __restrict__ V, int layer) {
    __shared__ float xs[64][68];   // tf32
    __shared__ float ws[64][68];   // tf32
    int tid = threadIdx.x;
    int r0 = blockIdx.x * 64;
    int s  = r0 >> 14;
    int o  = s*LAY + layer;
    const float* wq = wq_ + (size_t)o*DKk*64;
    const float* wk = wk_ + (size_t)o*DKk*64;
    const float* wv = wv_ + (size_t)o*64*64;

    int wid = tid >> 5, lane = tid & 31;
    int lr = lane >> 2, lc = lane & 3;
    int wm = wid >> 2, wn = wid & 3;          // 2(m) x 4(n)
    int mb = wm*32, nb = wn*16;

    for (int idx = tid; idx < 64*64; idx += 256) {
        int r = idx >> 6, c = idx & 63;
        int gr = r0 + r;
        int q  = gr & 16383;
        int g2 = q >> 10, n = q & 1023;
        int b = g2 >> 2, seg = g2 & 3;
        xs[r][c] = __uint_as_float(f2tf32(Z[(size_t)(s*TOK + ((b<<10)+n)*SG + seg)*HID + c]));
    }
    for (int chunk = 0; chunk < 2; chunk++) {
        __syncthreads();
        for (int idx = tid; idx < 64*64; idx += 256) {
            int r = idx >> 6, c = idx & 63;
            float v = (chunk == 0) ? (r < 32 ? wq[r*64 + c] : wk[(r-32)*64 + c]) : wv[r*64 + c];
            ws[r][c] = __uint_as_float(f2tf32(v));
        }
        __syncthreads();
        float acc[2][2][4];
#pragma unroll
        for (int t = 0; t < 2; t++)
#pragma unroll
            for (int j = 0; j < 2; j++)
#pragma unroll
                for (int q = 0; q < 4; q++) acc[t][j][q] = 0.f;
#pragma unroll
        for (int k0 = 0; k0 < 64; k0 += 8) {
            unsigned a[2][4];
#pragma unroll
            for (int t = 0; t < 2; t++) {
                int r = mb + 16*t + lr;
                a[t][0] = __float_as_uint(xs[r][k0+lc]);
                a[t][1] = __float_as_uint(xs[r+8][k0+lc]);
                a[t][2] = __float_as_uint(xs[r][k0+lc+4]);
                a[t][3] = __float_as_uint(xs[r+8][k0+lc+4]);
            }
#pragma unroll
            for (int j = 0; j < 2; j++) {
                unsigned b0 = __float_as_uint(ws[nb+8*j+lr][k0+lc]);
                unsigned bq = __float_as_uint(ws[nb+8*j+lr][k0+lc+4]);
#pragma unroll
                for (int t = 0; t < 2; t++)
                    mma_tf32(acc[t][j], a[t][0], a[t][1], a[t][2], a[t][3], b0, bq);
            }
        }
#pragma unroll
        for (int t = 0; t < 2; t++)
#pragma unroll
            for (int j = 0; j < 2; j++) {
                int c = nb + 8*j + 2*lc;
                int gr0 = r0 + mb + 16*t + lr;
#pragma unroll
                for (int half = 0; half < 2; half++) {
                    int gr = gr0 + 8*half;
                    float v0 = acc[t][j][2*half], v1 = acc[t][j][2*half+1];
                    if (chunk == 0) {
                        if (c < 32) { Q[(size_t)gr*32 + c] = v0;      Q[(size_t)gr*32 + c + 1] = v1; }
                        else        { K[(size_t)gr*32 + c - 32] = v0; K[(size_t)gr*32 + c - 31] = v1; }
                    } else        { V[(size_t)gr*64 + c] = v0;      V[(size_t)gr*64 + c + 1] = v1; }
                }
            }
    }
}

// ---------------- attention: tf32 tensor-core flash attention; dk=32, dv=64, N=1024/group ----------------
// K-tile 64. mode 0: plain write; mode 1: GA epilogue — Z = LN(att)*g+b + Z
// smem (floats): ps[64*68] | fct[64] | linv[64] | qs[64*36] | ks[64*36] | vt[64*68]
#define ATTN_SMEM_FLOATS (4352 + 64 + 64 + 2304 + 2304 + 4352)
__global__ __launch_bounds__(256) void attn_kernel(const float* __restrict__ Q,
        const float* __restrict__ K, const float* __restrict__ V,
        float* __restrict__ out, const float* __restrict__ g_, const float* __restrict__ bb_,
        int layer, int mode, float scale) {
    extern __shared__ float sm[];
    float* ps   = sm;               // [64][68]
    float* fct  = sm + 4352;        // [64]
    float* linv = sm + 4416;        // [64]
    float* qs   = sm + 4480;        // [64][36] tf32
    float* ks   = sm + 6784;        // [64][36] tf32
    float* vt   = sm + 9088;        // [64][68] tf32 (V transposed)
    float* os   = sm + 4480;        // [64][68] (mode1, aliases qs/ks/vt)

    int G  = blockIdx.x;
    int q0 = blockIdx.y * 64;
    int tid = threadIdx.x, wid = tid >> 5, lane = tid & 31;
    int lr = lane >> 2, lc = lane & 3;
    int wm = wid >> 1, wn = wid & 1;
    int mb = wm * 16;
    const float* Qg = Q + (size_t)G*NN*32;
    const float* Kg = K + (size_t)G*NN*32;
    const float* Vg = V + (size_t)G*NN*64;

    for (int idx = tid; idx < 64*32; idx += 256) {
        int r = idx >> 5, d = idx & 31;
        qs[r*36 + d] = __uint_as_float(f2tf32(scale * Qg[(size_t)(q0+r)*32 + d]));
    }

    int sr = wid*8 + lr;   // softmax row; lc selects 16-col group
    float m8 = -1e30f, l8 = 0.f;

    float oacc[4][4];
#pragma unroll
    for (int t = 0; t < 4; t++)
#pragma unroll
        for (int q = 0; q < 4; q++) oacc[t][q] = 0.f;

    for (int kt = 0; kt < NN; kt += 64) {
        __syncthreads();
        for (int idx = tid; idx < 64*32; idx += 256) {
            int k = idx >> 5, d = idx & 31;
            ks[k*36 + d] = __uint_as_float(f2tf32(Kg[(size_t)(kt+k)*32 + d]));
        }
        for (int idx = tid; idx < 64*64; idx += 256) {
            int k = idx >> 6, c = idx & 63;
            vt[c*68 + k] = __uint_as_float(f2tf32(Vg[(size_t)(kt+k)*64 + c]));
        }
        __syncthreads();

        // ---- S = Q @ K^T (64x64), warp grid 4(m) x 2(n of 32) ----
        float sacc[4][4];
#pragma unroll
        for (int t = 0; t < 4; t++)
#pragma unroll
            for (int q = 0; q < 4; q++) sacc[t][q] = 0.f;
#pragma unroll
        for (int k0 = 0; k0 < 32; k0 += 8) {
            unsigned a0 = __float_as_uint(qs[(mb+lr)*36   + k0+lc]);
            unsigned a1 = __float_as_uint(qs[(mb+lr+8)*36 + k0+lc]);
            unsigned a2 = __float_as_uint(qs[(mb+lr)*36   + k0+lc+4]);
            unsigned a3 = __float_as_uint(qs[(mb+lr+8)*36 + k0+lc+4]);
#pragma unroll
            for (int t = 0; t < 4; t++) {
                int n0 = 32*wn + 8*t;
                unsigned b0 = __float_as_uint(ks[(n0+lr)*36 + k0+lc]);
                unsigned b1 = __float_as_uint(ks[(n0+lr)*36 + k0+lc+4]);
                mma_tf32(sacc[t], a0, a1, a2, a3, b0, b1);
            }
        }
#pragma unroll
        for (int t = 0; t < 4; t++) {
            int col = 32*wn + 8*t + 2*lc;
            ps[(mb+lr)*68   + col]     = sacc[t][0];
            ps[(mb+lr)*68   + col + 1] = sacc[t][1];
            ps[(mb+lr+8)*68 + col]     = sacc[t][2];
            ps[(mb+lr+8)*68 + col + 1] = sacc[t][3];
        }
        __syncthreads();

        // ---- online softmax: thread owns row sr, 16 cols [16*lc, 16*lc+16) ----
        {
            float4 v0 = *(const float4*)&ps[sr*68 + 16*lc];
            float4 v1 = *(const float4*)&ps[sr*68 + 16*lc + 4];
            float4 v2 = *(const float4*)&ps[sr*68 + 16*lc + 8];
            float4 v3 = *(const float4*)&ps[sr*68 + 16*lc + 12];
            float tm = fmaxf(fmaxf(fmaxf(v0.x, v0.y), fmaxf(v0.z, v0.w)),
                             fmaxf(fmaxf(v1.x, v1.y), fmaxf(v1.z, v1.w)));
            tm = fmaxf(tm, fmaxf(fmaxf(fmaxf(v2.x, v2.y), fmaxf(v2.z, v2.w)),
                                 fmaxf(fmaxf(v3.x, v3.y), fmaxf(v3.z, v3.w))));
            tm = fmaxf(tm, __shfl_xor_sync(0xffffffffu, tm, 1));
            tm = fmaxf(tm, __shfl_xor_sync(0xffffffffu, tm, 2));
            float newm = fmaxf(m8, tm);
            float f = __expf(m8 - newm);
            m8 = newm;
            float p[16];
            p[0]=__expf(v0.x-newm); p[1]=__expf(v0.y-newm); p[2]=__expf(v0.z-newm); p[3]=__expf(v0.w-newm);
            p[4]=__expf(v1.x-newm); p[5]=__expf(v1.y-newm); p[6]=__expf(v1.z-newm); p[7]=__expf(v1.w-newm);
            p[8]=__expf(v2.x-newm); p[9]=__expf(v2.y-newm); p[10]=__expf(v2.z-newm); p[11]=__expf(v2.w-newm);
            p[12]=__expf(v3.x-newm); p[13]=__expf(v3.y-newm); p[14]=__expf(v3.z-newm); p[15]=__expf(v3.w-newm);
            float psum = 0.f;
#pragma unroll
            for (int i = 0; i < 16; i++) psum += p[i];
            psum += __shfl_xor_sync(0xffffffffu, psum, 1);
            psum += __shfl_xor_sync(0xffffffffu, psum, 2);
            l8 = l8 * f + psum;
            float4 w0, w1, w2, w3;
            w0.x=__uint_as_float(f2tf32(p[0]));  w0.y=__uint_as_float(f2tf32(p[1]));
            w0.z=__uint_as_float(f2tf32(p[2]));  w0.w=__uint_as_float(f2tf32(p[3]));
            w1.x=__uint_as_float(f2tf32(p[4]));  w1.y=__uint_as_float(f2tf32(p[5]));
            w1.z=__uint_as_float(f2tf32(p[6]));  w1.w=__uint_as_float(f2tf32(p[7]));
            w2.x=__uint_as_float(f2tf32(p[8]));  w2.y=__uint_as_float(f2tf32(p[9]));
            w2.z=__uint_as_float(f2tf32(p[10])); w2.w=__uint_as_float(f2tf32(p[11]));
            w3.x=__uint_as_float(f2tf32(p[12])); w3.y=__uint_as_float(f2tf32(p[13]));
            w3.z=__uint_as_float(f2tf32(p[14])); w3.w=__uint_as_float(f2tf32(p[15]));
            *(float4*)&ps[sr*68 + 16*lc]      = w0;
            *(float4*)&ps[sr*68 + 16*lc + 4]  = w1;
            *(float4*)&ps[sr*68 + 16*lc + 8]  = w2;
            *(float4*)&ps[sr*68 + 16*lc + 12] = w3;
            if (lc == 0) fct[sr] = f;
        }
        __syncthreads();

        // ---- O += P @ V (64x64), warp grid 4(m) x 2(n of 32) ----
        {
            float f0 = fct[mb+lr], f1 = fct[mb+lr+8];
#pragma unroll
            for (int t = 0; t < 4; t++) {
                oacc[t][0] *= f0; oacc[t][1] *= f0;
                oacc[t][2] *= f1; oacc[t][3] *= f1;
            }
        }
#pragma unroll
        for (int k0 = 0; k0 < 64; k0 += 8) {
            unsigned a0 = __float_as_uint(ps[(mb+lr)*68   + k0+lc]);
            unsigned a1 = __float_as_uint(ps[(mb+lr+8)*68 + k0+lc]);
            unsigned a2 = __float_as_uint(ps[(mb+lr)*68   + k0+lc+4]);
            unsigned a3 = __float_as_uint(ps[(mb+lr+8)*68 + k0+lc+4]);
#pragma unroll
            for (int t = 0; t < 4; t++) {
                int n0 = 32*wn + 8*t;
                unsigned b0 = __float_as_uint(vt[(n0+lr)*68 + k0+lc]);
                unsigned b1 = __float_as_uint(vt[(n0+lr)*68 + k0+lc+4]);
                mma_tf32(oacc[t], a0, a1, a2, a3, b0, b1);
            }
        }
    }

    if (lc == 0) linv[sr] = 1.f / l8;
    __syncthreads();

    float i0 = linv[mb+lr], i1 = linv[mb+lr+8];
    if (mode == 0) {
#pragma unroll
        for (int t = 0; t < 4; t++) {
            int col = 32*wn + 8*t + 2*lc;
            float* o0 = &out[(size_t)(G*NN + q0 + mb + lr)*64 + col];
            float* o1 = &out[(size_t)(G*NN + q0 + mb + lr + 8)*64 + col];
            o0[0] = oacc[t][0]*i0; o0[1] = oacc[t][1]*i0;
            o1[0] = oacc[t][2]*i1; o1[1] = oacc[t][3]*i1;
        }
    } else {
#pragma unroll
        for (int t = 0; t < 4; t++) {
            int col = 32*wn + 8*t + 2*lc;
            os[(mb+lr)*68 + col]     = oacc[t][0]*i0;
            os[(mb+lr)*68 + col + 1] = oacc[t][1]*i0;
            os[(mb+lr+8)*68 + col]     = oacc[t][2]*i1;
            os[(mb+lr+8)*68 + col + 1] = oacc[t][3]*i1;
        }
        __syncthreads();
        int sIdx = G >> 4, g2 = G & 15;
        int b = g2 >> 2, seg = g2 & 3;
        int o = sIdx*LAY + layer;
        const float* gg = g_  + (size_t)o*64;
        const float* bbp = bb_ + (size_t)o*64;
#pragma unroll
        for (int rr = 0; rr < 8; rr++) {
            int r = wid*8 + rr;
            int n = q0 + r;
            float* zp = out + (size_t)(sIdx*TOK + ((b<<10)+n)*SG + seg)*HID;
            float v0 = os[r*68 + lane], v1 = os[r*68 + lane + 32];
            float ssum = v0 + v1, qq = v0*v0 + v1*v1;
#pragma unroll
            for (int off = 16; off; off >>= 1) {
                ssum += __shfl_xor_sync(0xffffffffu, ssum, off);
                qq   += __shfl_xor_sync(0xffffffffu, qq, off);
            }
            float mean = ssum * (1.f/64.f);
            float var  = qq * (1.f/64.f) - mean*mean;
            float rstd = rsqrtf(var + 1e-5f);
            zp[lane]      = (v0 - mean)*rstd*gg[lane]    + bbp[lane]    + zp[lane];
            zp[lane + 32] = (v1 - mean)*rstd*gg[lane+32] + bbp[lane+32] + zp[lane + 32];
        }
    }
}

// ---------------- mean-pool over segments + concat (both streams) ----------------
__global__ __launch_bounds__(256) void pool_kernel(const float* __restrict__ Z,
        float* __restrict__ ENC) {
    int idx = blockIdx.x * 256 + threadIdx.x;   // over 2*B*NN*64
    int s  = idx >> 18;
    int rem = idx & 262143;
    int bn = rem >> 6, h = rem & 63;
    const float* zp = Z + (size_t)(s*TOK + bn*4)*64;
    float a = 0.25f * (zp[0*64+h] + zp[1*64+h] + zp[2*64+h] + zp[3*64+h]);
    ENC[(size_t)bn*128 + s*64 + h] = a;
}

// ---------------- final cross-attention projections (in dim = 128) ----------------
__global__ __launch_bounds__(256) void fproj_kernel(const float* __restrict__ ENC,
        const float* __restrict__ wq, const float* __restrict__ wk, const float* __restrict__ wv,
        float* __restrict__ Q, float* __restrict__ K, float* __restrict__ V) {
    __shared__ float xs[64][68];
    __shared__ float ws[64][68];
    int tid = threadIdx.x;
    int r0 = blockIdx.x * 64;
    int ty = tid >> 4, tx = tid & 15;
    float acc[2][4][4];
#pragma unroll
    for (int oc = 0; oc < 2; oc++)
#pragma unroll
        for (int i = 0; i < 4; i++)
#pragma unroll
            for (int j = 0; j < 4; j++) acc[oc][i][j] = 0.f;

    for (int kc = 0; kc < 2; kc++) {
        __syncthreads();
        for (int idx = tid; idx < 64*64; idx += 256) {
            int r = idx >> 6, c = idx & 63;
            xs[r][c] = ENC[(size_t)(r0+r)*128 + kc*64 + c];
        }
        for (int oc = 0; oc < 2; oc++) {
            __syncthreads();
            for (int idx = tid; idx < 64*64; idx += 256) {
                int r = idx >> 6, c = idx & 63;
                int gc = oc*64 + r;
                int k  = kc*64 + c;
                ws[r][c] = (gc < 32) ? wq[gc*128 + k] : (gc < 64) ? wk[(gc-32)*128 + k] : wv[(gc-64)*128 + k];
            }
            __syncthreads();
#pragma unroll 4
            for (int k = 0; k < 64; k += 4) {
                float4 xv[4], wv4[4];
#pragma unroll
                for (int i = 0; i < 4; i++) xv[i] = *(const float4*)&xs[4*ty+i][k];
#pragma unroll
                for (int j = 0; j < 4; j++) wv4[j] = *(const float4*)&ws[tx+16*j][k];
#pragma unroll
                for (int i = 0; i < 4; i++)
#pragma unroll
                    for (int j = 0; j < 4; j++)
                        acc[oc][i][j] += xv[i].x*wv4[j].x + xv[i].y*wv4[j].y + xv[i].z*wv4[j].z + xv[i].w*wv4[j].w;
            }
        }
    }
#pragma unroll
    for (int oc = 0; oc < 2; oc++)
#pragma unroll
        for (int i = 0; i < 4; i++) {
            int gr = r0 + 4*ty + i;
#pragma unroll
            for (int j = 0; j < 4; j++) {
                int gc = oc*64 + tx + 16*j;
                float v = acc[oc][i][j];
                if (gc < 32)      Q[(size_t)gr*32 + gc] = v;
                else if (gc < 64) K[(size_t)gr*32 + gc - 32] = v;
                else              V[(size_t)gr*64 + gc - 64] = v;
            }
        }
}

// ---------------- host launcher ----------------
extern "C" void kernel_launch(void* const* d_in, const int* in_sizes, int n_in,
                              void* d_out, int out_size) {
    const float* traffic  = (const float*)d_in[0];
    const float* user     = (const float*)d_in[1];
    const float* patch_w  = (const float*)d_in[2];
    const float* patch_b  = (const float*)d_in[3];
    const float* mha_w    = (const float*)d_in[4];
    const float* mha_b    = (const float*)d_in[5];
    const float* out_w    = (const float*)d_in[6];
    const float* out_b    = (const float*)d_in[7];
    const float* ff1_w    = (const float*)d_in[8];
    const float* ff1_b    = (const float*)d_in[9];
    const float* ff2_w    = (const float*)d_in[10];
    const float* ff2_b    = (const float*)d_in[11];
    const float* ln1_g    = (const float*)d_in[12];
    const float* ln1_b    = (const float*)d_in[13];
    const float* ln2_g    = (const float*)d_in[14];
    const float* ln2_b    = (const float*)d_in[15];
    const float* ga_wq    = (const float*)d_in[16];
    const float* ga_wk    = (const float*)d_in[17];
    const float* ga_wv    = (const float*)d_in[18];
    const float* ga_ff1_w = (const float*)d_in[19];
    const float* ga_ff1_b = (const float*)d_in[20];
    const float* ga_ff2_w = (const float*)d_in[21];
    const float* ga_ff2_b = (const float*)d_in[22];
    const float* ga_ln1_g = (const float*)d_in[23];
    const float* ga_ln1_b = (const float*)d_in[24];
    const float* ga_ln2_g = (const float*)d_in[25];
    const float* ga_ln2_b = (const float*)d_in[26];
    const float* ca_wq    = (const float*)d_in[27];
    const float* ca_wk    = (const float*)d_in[28];
    const float* ca_wv    = (const float*)d_in[29];

    float *Z, *Qb, *Kb, *Vb, *ENC, *Q2, *K2, *V2;
    cudaGetSymbolAddress((void**)&Z,   d_Z);
    cudaGetSymbolAddress((void**)&Qb,  d_Qb);
    cudaGetSymbolAddress((void**)&Kb,  d_Kb);
    cudaGetSymbolAddress((void**)&Vb,  d_Vb);
    cudaGetSymbolAddress((void**)&ENC, d_ENC);
    cudaGetSymbolAddress((void**)&Q2,  d_Q2);
    cudaGetSymbolAddress((void**)&K2,  d_K2);
    cudaGetSymbolAddress((void**)&V2,  d_V2);

    const int MHA_SMEM  = MHA_SMEM_FLOATS * 4;    // 111,616 B
    const int FF_SMEM   = FF_SMEM_FLOATS * 4;     // 104,448 B -> 2 blocks/SM
    const int ATTN_SMEM = ATTN_SMEM_FLOATS * 4;   //  53,760 B -> 4 blocks/SM
    cudaFuncSetAttribute(mha_kernel,   cudaFuncAttributeMaxDynamicSharedMemorySize, MHA_SMEM);
    cudaFuncSetAttribute(ff_ln_kernel, cudaFuncAttributeMaxDynamicSharedMemorySize, FF_SMEM);
    cudaFuncSetAttribute(attn_kernel,  cudaFuncAttributeMaxDynamicSharedMemorySize, ATTN_SMEM);

    const float SCALE32 = 0.17677669529663687f;   // 1/sqrt(32)

    patch_kernel<<<2*B_*NN, 256>>>(traffic, user, patch_w, patch_b, Z);
    for (int i = 0; i < LAY; i++) {
        mha_kernel<<<2*TOK/64, 256, MHA_SMEM>>>(Z, mha_w, mha_b, out_w, out_b, ln1_g, ln1_b, i);
        ff_ln_kernel<<<2*TOK/128, 256, FF_SMEM>>>(Z, ff1_w, ff1_b, ff2_w, ff2_b, ln2_g, ln2_b, i);
        ga_qkv_kernel<<<2*TOK/64, 256>>>(Z, ga_wq, ga_wk, ga_wv, Qb, Kb, Vb, i);
        attn_kernel<<<dim3(2*GRP, NN/64), 256, ATTN_SMEM>>>(Qb, Kb, Vb, Z, ga_ln1_g, ga_ln1_b, i, 1, SCALE32);
        ff_ln_kernel<<<2*TOK/128, 256, FF_SMEM>>>(Z, ga_ff1_w, ga_ff1_b, ga_ff2_w, ga_ff2_b, ga_ln2_g, ga_ln2_b, i);
    }
    pool_kernel<<<2*B_*NN*HID/256, 256>>>(Z, ENC);
    fproj_kernel<<<B_*NN/64, 256>>>(ENC, ca_wq, ca_wk, ca_wv, Q2, K2, V2);
    attn_kernel<<<dim3(B_, NN/64), 256, ATTN_SMEM>>>(Q2, K2, V2, (float*)d_out, (const float*)0, (const float*)0, 0, 0, SCALE32);
}

// round 13
// speedup vs baseline: 1.0977x; 1.0977x over previous
#include <cuda_runtime.h>
#include <math.h>

#define B_   4
#define SEQ_ 12
#define NN   1024
#define SL   3
#define SG   4
#define HID  64
#define FFD  2048
#define DKk  32
#define LAY  2
#define TOK  (B_*NN*SG)   /* 16384 per stream */
#define GRP  (B_*SG)      /* 16 per stream */

// ---------------- scratch (static device memory) ----------------
__device__ float d_Z[2*TOK*HID];          // [s][b][n][seg][h]
__device__ float d_Qb[2*GRP*NN*DKk];
__device__ float d_Kb[2*GRP*NN*DKk];
__device__ float d_Vb[2*GRP*NN*HID];
__device__ float d_ENC[B_*NN*2*HID];
__device__ float d_Q2[B_*NN*DKk];
__device__ float d_K2[B_*NN*DKk];
__device__ float d_V2[B_*NN*HID];

// ---------------- tf32 / cp.async helpers ----------------
__device__ __forceinline__ unsigned f2tf32(float x) {
    unsigned r;
    asm("cvt.rna.tf32.f32 %0, %1;" : "=r"(r) : "f"(x));
    return r;
}
__device__ __forceinline__ void mma_tf32(float* c,
        unsigned a0, unsigned a1, unsigned a2, unsigned a3,
        unsigned b0, unsigned b1) {
    asm volatile("mma.sync.aligned.m16n8k8.row.col.f32.tf32.tf32.f32 "
        "{%0,%1,%2,%3}, {%4,%5,%6,%7}, {%8,%9}, {%0,%1,%2,%3};"
        : "+f"(c[0]), "+f"(c[1]), "+f"(c[2]), "+f"(c[3])
        : "r"(a0), "r"(a1), "r"(a2), "r"(a3), "r"(b0), "r"(b1));
}
__device__ __forceinline__ void cp_async16(float* smem_dst, const float* gmem_src) {
    unsigned saddr = (unsigned)__cvta_generic_to_shared(smem_dst);
    asm volatile("cp.async.cg.shared.global [%0], [%1], 16;" :: "r"(saddr), "l"(gmem_src));
}
#define CP_COMMIT() asm volatile("cp.async.commit_group;")
#define CP_WAIT0()  asm volatile("cp.async.wait_group 0;")

// ---------------- patch embedding + positional encoding (both streams) ----------------
__global__ __launch_bounds__(256) void patch_kernel(const float* __restrict__ traffic,
                                                    const float* __restrict__ user,
                                                    const float* __restrict__ pw,
                                                    const float* __restrict__ pb,
                                                    float* __restrict__ Z) {
    int blk = blockIdx.x;                // 0..8191
    int s   = blk >> 12;
    int bn  = blk & 4095;
    int b   = bn >> 10, n = bn & 1023;
    const float* x = s ? user : traffic;
    const float* pws = pw + s*HID*SL;
    const float* pbs = pb + s*HID;
    int t   = threadIdx.x;
    int seg = t >> 6, h = t & 63;
    float acc = pbs[h];
#pragma unroll
    for (int l = 0; l < SL; l++)
        acc += pws[h*SL + l] * x[(b*SEQ_ + seg*SL + l)*NN + n];
    int he = h & ~1;
    float dv = expf(-(float)he * (9.210340371976184f / (float)HID));
    float ang = (float)seg * dv;
    acc += (h & 1) ? cosf(ang) : sinf(ang);
    Z[(size_t)(s*TOK + bn*SG + seg)*HID + h] = acc;
}

// ---------------- temporal encoder: MHA + residual + LN1; 64 tokens / block ----------------
// GEMMs (QKV, out-proj) on tf32 tensor cores; 4x4 attention core scalar.
#define MHA_SMEM_FLOATS (4352 + 4352 + 12800 + 2048 + 4352)
__global__ __launch_bounds__(256) void mha_kernel(float* __restrict__ Z,
        const float* __restrict__ mw_, const float* __restrict__ mb_,
        const float* __restrict__ ow_, const float* __restrict__ ob_,
        const float* __restrict__ g1_, const float* __restrict__ b1_, int layer) {
    extern __shared__ float sm[];
    float (*xs)[68]  = (float(*)[68])sm;
    float (*wb)[68]  = (float(*)[68])(sm + 4352);
    float (*qkv)[200]= (float(*)[200])(sm + 8704);
    float *ps        = sm + 21504;
    float (*os)[68]  = (float(*)[68])(sm + 23552);

    int tid = threadIdx.x;
    int s  = blockIdx.x >> 8;                 // 512 blocks, 256 per stream
    int o  = s*LAY + layer;
    const float* mw = mw_ + (size_t)o*192*64;
    const float* mb = mb_ + (size_t)o*192;
    const float* ow = ow_ + (size_t)o*64*64;
    const float* ob = ob_ + (size_t)o*64;
    const float* g1 = g1_ + (size_t)o*64;
    const float* b1 = b1_ + (size_t)o*64;
    size_t t0 = (size_t)blockIdx.x * 64;
    float* zb = Z + t0 * HID;

    int wid = tid >> 5, lane = tid & 31;
    int lr = lane >> 2, lc = lane & 3;
    int wm = wid >> 2, wn = wid & 3;          // warp grid 2(m) x 4(n)
    int mb2 = wm*32, nb = wn*16;

    for (int idx = tid; idx < 64*16; idx += 256) {
        int r = idx >> 4, c4 = idx & 15;
        *(float4*)&xs[r][4*c4] = *(const float4*)&zb[(size_t)r*64 + 4*c4];
    }

    // ---- QKV = X @ W^T + b  (3 chunks of 64 cols), tf32 mma ----
    for (int cc = 0; cc < 3; cc++) {
        __syncthreads();
        for (int idx = tid; idx < 64*16; idx += 256) {
            int r = idx >> 4, c4 = idx & 15;
            float4 v = *(const float4*)&mw[(size_t)(cc*64 + r)*64 + 4*c4];
            wb[r][4*c4+0] = __uint_as_float(f2tf32(v.x));
            wb[r][4*c4+1] = __uint_as_float(f2tf32(v.y));
            wb[r][4*c4+2] = __uint_as_float(f2tf32(v.z));
            wb[r][4*c4+3] = __uint_as_float(f2tf32(v.w));
        }
        __syncthreads();
        float acc[2][2][4];
#pragma unroll
        for (int j = 0; j < 2; j++) {
            int c = nb + 8*j + 2*lc;
            float bv0 = mb[cc*64 + c], bv1 = mb[cc*64 + c + 1];
#pragma unroll
            for (int t = 0; t < 2; t++) {
                acc[t][j][0] = bv0; acc[t][j][1] = bv1;
                acc[t][j][2] = bv0; acc[t][j][3] = bv1;
            }
        }
#pragma unroll
        for (int k0 = 0; k0 < 64; k0 += 8) {
            unsigned a[2][4];
#pragma unroll
            for (int t = 0; t < 2; t++) {
                int r = mb2 + 16*t + lr;
                a[t][0] = f2tf32(xs[r][k0+lc]);
                a[t][1] = f2tf32(xs[r+8][k0+lc]);
                a[t][2] = f2tf32(xs[r][k0+lc+4]);
                a[t][3] = f2tf32(xs[r+8][k0+lc+4]);
            }
#pragma unroll
            for (int j = 0; j < 2; j++) {
                unsigned b0 = __float_as_uint(wb[nb+8*j+lr][k0+lc]);
                unsigned bq = __float_as_uint(wb[nb+8*j+lr][k0+lc+4]);
#pragma unroll
                for (int t = 0; t < 2; t++)
                    mma_tf32(acc[t][j], a[t][0], a[t][1], a[t][2], a[t][3], b0, bq);
            }
        }
#pragma unroll
        for (int t = 0; t < 2; t++)
#pragma unroll
            for (int j = 0; j < 2; j++) {
                int r = mb2 + 16*t + lr, c = cc*64 + nb + 8*j + 2*lc;
                qkv[r][c]     = acc[t][j][0];
                qkv[r][c+1]   = acc[t][j][1];
                qkv[r+8][c]   = acc[t][j][2];
                qkv[r+8][c+1] = acc[t][j][3];
            }
    }
    __syncthreads();

    // ---- scores + softmax (scalar; tiny) ----
    for (int T = tid; T < 512; T += 256) {
        int g = T >> 5, h = (T >> 2) & 7, i = T & 3;
        const float* q = &qkv[g*4 + i][h*8];
        float sc[4];
#pragma unroll
        for (int j = 0; j < 4; j++) {
            const float* kk = &qkv[g*4 + j][64 + h*8];
            float a = 0.f;
#pragma unroll
            for (int d = 0; d < 8; d++) a += q[d] * kk[d];
            sc[j] = a * 0.3535533905932738f;
        }
        float m = fmaxf(fmaxf(sc[0], sc[1]), fmaxf(sc[2], sc[3]));
        float e0 = __expf(sc[0]-m), e1 = __expf(sc[1]-m), e2 = __expf(sc[2]-m), e3 = __expf(sc[3]-m);
        float inv = 1.f / (e0+e1+e2+e3);
        ps[T*4+0] = e0*inv; ps[T*4+1] = e1*inv; ps[T*4+2] = e2*inv; ps[T*4+3] = e3*inv;
    }
    __syncthreads();

    // ---- O = att @ V (scalar; tiny) ----
    {
        int ty = tid >> 4, tx = tid & 15;
#pragma unroll
        for (int i = 0; i < 4; i++) {
            int r = 4*ty + i;
            int g = r >> 2, ii = r & 3;
#pragma unroll
            for (int j = 0; j < 4; j++) {
                int c = tx + 16*j;
                int h = c >> 3;
                const float* a = ps + (((g*8 + h)*4) + ii)*4;
                os[r][c] = a[0]*qkv[g*4+0][128+c] + a[1]*qkv[g*4+1][128+c]
                         + a[2]*qkv[g*4+2][128+c] + a[3]*qkv[g*4+3][128+c];
            }
        }
    }
    __syncthreads();

    // ---- out proj + residual, tf32 mma ----
    for (int idx = tid; idx < 64*16; idx += 256) {
        int r = idx >> 4, c4 = idx & 15;
        float4 v = *(const float4*)&ow[(size_t)r*64 + 4*c4];
        wb[r][4*c4+0] = __uint_as_float(f2tf32(v.x));
        wb[r][4*c4+1] = __uint_as_float(f2tf32(v.y));
        wb[r][4*c4+2] = __uint_as_float(f2tf32(v.z));
        wb[r][4*c4+3] = __uint_as_float(f2tf32(v.w));
    }
    __syncthreads();
    {
        float acc[2][2][4];
#pragma unroll
        for (int j = 0; j < 2; j++) {
            int c = nb + 8*j + 2*lc;
            float bv0 = ob[c], bv1 = ob[c+1];
#pragma unroll
            for (int t = 0; t < 2; t++) {
                acc[t][j][0] = bv0; acc[t][j][1] = bv1;
                acc[t][j][2] = bv0; acc[t][j][3] = bv1;
            }
        }
#pragma unroll
        for (int k0 = 0; k0 < 64; k0 += 8) {
            unsigned a[2][4];
#pragma unroll
            for (int t = 0; t < 2; t++) {
                int r = mb2 + 16*t + lr;
                a[t][0] = f2tf32(os[r][k0+lc]);
                a[t][1] = f2tf32(os[r+8][k0+lc]);
                a[t][2] = f2tf32(os[r][k0+lc+4]);
                a[t][3] = f2tf32(os[r+8][k0+lc+4]);
            }
#pragma unroll
            for (int j = 0; j < 2; j++) {
                unsigned b0 = __float_as_uint(wb[nb+8*j+lr][k0+lc]);
                unsigned bq = __float_as_uint(wb[nb+8*j+lr][k0+lc+4]);
#pragma unroll
                for (int t = 0; t < 2; t++)
                    mma_tf32(acc[t][j], a[t][0], a[t][1], a[t][2], a[t][3], b0, bq);
            }
        }
        __syncthreads();
#pragma unroll
        for (int t = 0; t < 2; t++)
#pragma unroll
            for (int j = 0; j < 2; j++) {
                int r = mb2 + 16*t + lr, c = nb + 8*j + 2*lc;
                xs[r][c]     += acc[t][j][0];
                xs[r][c+1]   += acc[t][j][1];
                xs[r+8][c]   += acc[t][j][2];
                xs[r+8][c+1] += acc[t][j][3];
            }
    }
    __syncthreads();
    // ---- LN ----
    int w = tid >> 5, lane2 = tid & 31;
#pragma unroll
    for (int rr = 0; rr < 8; rr++) {
        int r = w*8 + rr;
        float v0 = xs[r][lane2], v1 = xs[r][lane2+32];
        float ssum = v0 + v1, q = v0*v0 + v1*v1;
#pragma unroll
        for (int off = 16; off; off >>= 1) { ssum += __shfl_xor_sync(0xffffffffu, ssum, off); q += __shfl_xor_sync(0xffffffffu, q, off); }
        float mean = ssum * (1.f/64.f);
        float var  = q * (1.f/64.f) - mean*mean;
        float rstd = rsqrtf(var + 1e-5f);
        zb[(size_t)r*64 + lane2]      = (v0 - mean)*rstd*g1[lane2]    + b1[lane2];
        zb[(size_t)r*64 + lane2 + 32] = (v1 - mean)*rstd*g1[lane2+32] + b1[lane2+32];
    }
}

// ---------------- fused FF + residual + LN: tf32 mma, 128 tokens/block, FF chunk 128 ----------------
// cp.async weight pipeline: w1s single-buffer (prefetched during GEMM2 while dead),
// w2s double-buffer. Weights raw fp32 in smem; tf32 cvt at fragment load.
// smem floats: xs[128][68] | hs[128][132] | w1s[128][68] | w2s[2][64][132]
#define FF_SMEM_FLOATS (8704 + 16896 + 8704 + 2*8448)
__global__ __launch_bounds__(256) void ff_ln_kernel(float* __restrict__ Z,
        const float* __restrict__ w1_, const float* __restrict__ b1_,
        const float* __restrict__ w2_, const float* __restrict__ b2_,
        const float* __restrict__ g_, const float* __restrict__ bb_, int layer) {
    extern __shared__ float sm[];
    float (*xs)[68]  = (float(*)[68])sm;
    float (*hs)[132] = (float(*)[132])(sm + 8704);
    float (*w1s)[68] = (float(*)[68])(sm + 25600);
    float* w2base    = sm + 34304;              // two [64][132] buffers

    int tid = threadIdx.x;
    int s   = blockIdx.x >> 7;           // 256 blocks, 128 per stream
    int o   = s*LAY + layer;
    const float* w1 = w1_ + (size_t)o*FFD*64;
    const float* b1 = b1_ + (size_t)o*FFD;
    const float* w2 = w2_ + (size_t)o*64*FFD;
    const float* b2 = b2_ + (size_t)o*64;
    const float* g  = g_  + (size_t)o*64;
    const float* bb = bb_ + (size_t)o*64;
    size_t t0 = (size_t)blockIdx.x * 128;

    int wid  = tid >> 5, lane = tid & 31;
    int lr = lane >> 2, lc = lane & 3;           // fragment row/col
    int wm = wid >> 2, wn = wid & 3;             // warp grid 2 x 4
    int mb = wm*64, nbh = wn*32, nbo = wn*16;

    for (int idx = tid; idx < 128*16; idx += 256) {
        int r = idx >> 4, c4 = idx & 15;
        *(float4*)&xs[r][4*c4] = *(const float4*)&Z[(t0 + r)*64 + 4*c4];
    }

    // prefetch chunk 0 weights (raw fp32)
    for (int idx = tid; idx < 2048; idx += 256) {
        int r = idx >> 4, c4 = idx & 15;
        cp_async16(&w1s[r][4*c4], &w1[(size_t)r*64 + 4*c4]);
    }
    for (int idx = tid; idx < 2048; idx += 256) {
        int r = idx >> 5, c4 = idx & 31;
        cp_async16(&w2base[r*132 + 4*c4], &w2[(size_t)r*FFD + 4*c4]);
    }
    CP_COMMIT();
    CP_WAIT0();
    __syncthreads();

    float oacc[4][2][4];
#pragma unroll
    for (int t = 0; t < 4; t++)
#pragma unroll
        for (int j = 0; j < 2; j++)
#pragma unroll
            for (int q = 0; q < 4; q++) oacc[t][j][q] = 0.f;

    for (int ci = 0; ci < FFD/128; ci++) {
        int fc = ci * 128;
        float* w2cur = w2base + (ci & 1) * 8448;

        // ---- H[128][128] = relu(X @ W1c^T + b1c), tf32 mma ----
        float hacc[4][4][4];
#pragma unroll
        for (int t = 0; t < 4; t++)
#pragma unroll
            for (int j = 0; j < 4; j++)
#pragma unroll
                for (int q = 0; q < 4; q++) hacc[t][j][q] = 0.f;

#pragma unroll
        for (int k0 = 0; k0 < 64; k0 += 8) {
            unsigned a[4][4];
#pragma unroll
            for (int t = 0; t < 4; t++) {
                int r = mb + 16*t + lr;
                a[t][0] = f2tf32(xs[r][k0+lc]);
                a[t][1] = f2tf32(xs[r+8][k0+lc]);
                a[t][2] = f2tf32(xs[r][k0+lc+4]);
                a[t][3] = f2tf32(xs[r+8][k0+lc+4]);
            }
#pragma unroll
            for (int j = 0; j < 4; j++) {
                unsigned b0 = f2tf32(w1s[nbh+8*j+lr][k0+lc]);
                unsigned bq = f2tf32(w1s[nbh+8*j+lr][k0+lc+4]);
#pragma unroll
                for (int t = 0; t < 4; t++)
                    mma_tf32(hacc[t][j], a[t][0], a[t][1], a[t][2], a[t][3], b0, bq);
            }
        }
#pragma unroll
        for (int j = 0; j < 4; j++) {
            int c = nbh + 8*j + 2*lc;
            float bv0 = b1[fc + c], bv1 = b1[fc + c + 1];
#pragma unroll
            for (int t = 0; t < 4; t++) {
                int r = mb + 16*t + lr;
                hs[r][c]     = __uint_as_float(f2tf32(fmaxf(hacc[t][j][0] + bv0, 0.f)));
                hs[r][c+1]   = __uint_as_float(f2tf32(fmaxf(hacc[t][j][1] + bv1, 0.f)));
                hs[r+8][c]   = __uint_as_float(f2tf32(fmaxf(hacc[t][j][2] + bv0, 0.f)));
                hs[r+8][c+1] = __uint_as_float(f2tf32(fmaxf(hacc[t][j][3] + bv1, 0.f)));
            }
        }
        __syncthreads();   // hs ready; all warps past GEMM1 (w1s dead)

        // prefetch next chunk's weights while GEMM2 runs
        if (ci + 1 < FFD/128) {
            int fcn = fc + 128;
            float* w2nxt = w2base + ((ci + 1) & 1) * 8448;
            for (int idx = tid; idx < 2048; idx += 256) {
                int r = idx >> 4, c4 = idx & 15;
                cp_async16(&w1s[r][4*c4], &w1[(size_t)(fcn + r)*64 + 4*c4]);
            }
            for (int idx = tid; idx < 2048; idx += 256) {
                int r = idx >> 5, c4 = idx & 31;
                cp_async16(&w2nxt[r*132 + 4*c4], &w2[(size_t)r*FFD + fcn + 4*c4]);
            }
            CP_COMMIT();
        }

        // ---- O[128][64] += H @ W2c^T, tf32 mma ----
#pragma unroll
        for (int k0 = 0; k0 < 128; k0 += 8) {
            unsigned a[4][4];
#pragma unroll
            for (int t = 0; t < 4; t++) {
                int r = mb + 16*t + lr;
                a[t][0] = __float_as_uint(hs[r][k0+lc]);
                a[t][1] = __float_as_uint(hs[r+8][k0+lc]);
                a[t][2] = __float_as_uint(hs[r][k0+lc+4]);
                a[t][3] = __float_as_uint(hs[r+8][k0+lc+4]);
            }
#pragma unroll
            for (int j = 0; j < 2; j++) {
                unsigned b0 = f2tf32(w2cur[(nbo+8*j+lr)*132 + k0+lc]);
                unsigned bq = f2tf32(w2cur[(nbo+8*j+lr)*132 + k0+lc+4]);
#pragma unroll
                for (int t = 0; t < 4; t++)
                    mma_tf32(oacc[t][j], a[t][0], a[t][1], a[t][2], a[t][3], b0, bq);
            }
        }
        CP_WAIT0();        // next weights landed
        __syncthreads();   // hs free for overwrite; staged weights visible
    }

    // residual: each (r,c) has exactly one owner thread
#pragma unroll
    for (int j = 0; j < 2; j++) {
        int c = nbo + 8*j + 2*lc;
        float bv0 = b2[c], bv1 = b2[c+1];
#pragma unroll
        for (int t = 0; t < 4; t++) {
            int r = mb + 16*t + lr;
            xs[r][c]     += oacc[t][j][0] + bv0;
            xs[r][c+1]   += oacc[t][j][1] + bv1;
            xs[r+8][c]   += oacc[t][j][2] + bv0;
            xs[r+8][c+1] += oacc[t][j][3] + bv1;
        }
    }
    __syncthreads();
    int w = tid >> 5, lane2 = tid & 31;
#pragma unroll
    for (int rr = 0; rr < 16; rr++) {
        int r = w*16 + rr;
        float v0 = xs[r][lane2], v1 = xs[r][lane2+32];
        float ssum = v0 + v1, q = v0*v0 + v1*v1;
#pragma unroll
        for (int off = 16; off; off >>= 1) { ssum += __shfl_xor_sync(0xffffffffu, ssum, off); q += __shfl_xor_sync(0xffffffffu, q, off); }
        float mean = ssum * (1.f/64.f);
        float var  = q * (1.f/64.f) - mean*mean;
        float rstd = rsqrtf(var + 1e-5f);
        Z[(t0+r)*64 + lane2]      = (v0 - mean)*rstd*g[lane2]    + bb[lane2];
        Z[(t0+r)*64 + lane2 + 32] = (v1 - mean)*rstd*g[lane2+32] + bb[lane2+32];
    }
}

// ---------------- graph-attention QKV projection: tf32 mma, 64 rows/block ----------------
__global__ __launch_bounds__(256) void ga_qkv_kernel(const float* __restrict__ Z,
        const float* __restrict__ wq_, const float* __restrict__ wk_, const float* __restrict__ wv_,
        float* __restrict__ Q, float* __restrict__ K, float* __restrict__ V, int layer) {
    __shared__ float xs[64][68];   // tf32
    __shared__ float ws[64][68];   // tf32
    int tid = threadIdx.x;
    int r0 = blockIdx.x * 64;
    int s  = r0 >> 14;
    int o  = s*LAY + layer;
    const float* wq = wq_ + (size_t)o*DKk*64;
    const float* wk = wk_ + (size_t)o*DKk*64;
    const float* wv = wv_ + (size_t)o*64*64;

    int wid = tid >> 5, lane = tid & 31;
    int lr = lane >> 2, lc = lane & 3;
    int wm = wid >> 2, wn = wid & 3;          // 2(m) x 4(n)
    int mb = wm*32, nb = wn*16;

    for (int idx = tid; idx < 64*64; idx += 256) {
        int r = idx >> 6, c = idx & 63;
        int gr = r0 + r;
        int q  = gr & 16383;
        int g2 = q >> 10, n = q & 1023;
        int b = g2 >> 2, seg = g2 & 3;
        xs[r][c] = __uint_as_float(f2tf32(Z[(size_t)(s*TOK + ((b<<10)+n)*SG + seg)*HID + c]));
    }
    for (int chunk = 0; chunk < 2; chunk++) {
        __syncthreads();
        for (int idx = tid; idx < 64*64; idx += 256) {
            int r = idx >> 6, c = idx & 63;
            float v = (chunk == 0) ? (r < 32 ? wq[r*64 + c] : wk[(r-32)*64 + c]) : wv[r*64 + c];
            ws[r][c] = __uint_as_float(f2tf32(v));
        }
        __syncthreads();
        float acc[2][2][4];
#pragma unroll
        for (int t = 0; t < 2; t++)
#pragma unroll
            for (int j = 0; j < 2; j++)
#pragma unroll
                for (int q = 0; q < 4; q++) acc[t][j][q] = 0.f;
#pragma unroll
        for (int k0 = 0; k0 < 64; k0 += 8) {
            unsigned a[2][4];
#pragma unroll
            for (int t = 0; t < 2; t++) {
                int r = mb + 16*t + lr;
                a[t][0] = __float_as_uint(xs[r][k0+lc]);
                a[t][1] = __float_as_uint(xs[r+8][k0+lc]);
                a[t][2] = __float_as_uint(xs[r][k0+lc+4]);
                a[t][3] = __float_as_uint(xs[r+8][k0+lc+4]);
            }
#pragma unroll
            for (int j = 0; j < 2; j++) {
                unsigned b0 = __float_as_uint(ws[nb+8*j+lr][k0+lc]);
                unsigned bq = __float_as_uint(ws[nb+8*j+lr][k0+lc+4]);
#pragma unroll
                for (int t = 0; t < 2; t++)
                    mma_tf32(acc[t][j], a[t][0], a[t][1], a[t][2], a[t][3], b0, bq);
            }
        }
#pragma unroll
        for (int t = 0; t < 2; t++)
#pragma unroll
            for (int j = 0; j < 2; j++) {
                int c = nb + 8*j + 2*lc;
                int gr0 = r0 + mb + 16*t + lr;
#pragma unroll
                for (int half = 0; half < 2; half++) {
                    int gr = gr0 + 8*half;
                    float v0 = acc[t][j][2*half], v1 = acc[t][j][2*half+1];
                    if (chunk == 0) {
                        if (c < 32) { Q[(size_t)gr*32 + c] = v0;      Q[(size_t)gr*32 + c + 1] = v1; }
                        else        { K[(size_t)gr*32 + c - 32] = v0; K[(size_t)gr*32 + c - 31] = v1; }
                    } else        { V[(size_t)gr*64 + c] = v0;      V[(size_t)gr*64 + c + 1] = v1; }
                }
            }
    }
}

// ---------------- attention: tf32 tensor-core flash attention; dk=32, dv=64, N=1024/group ----------------
// mode 0: plain write to out[(G*NN+q)*64+c] ; mode 1: GA epilogue — Z = LN(att)*g+b + Z
__global__ __launch_bounds__(256) void attn_kernel(const float* __restrict__ Q,
        const float* __restrict__ K, const float* __restrict__ V,
        float* __restrict__ out, const float* __restrict__ g_, const float* __restrict__ bb_,
        int layer, int mode, float scale) {
    __shared__ float sm[8192];
    float* ps   = sm;               // [64][36]
    float* fct  = sm + 2304;        // [64]
    float* linv = sm + 2368;        // [64]
    float* qs   = sm + 2432;        // [64][36] tf32
    float* ks   = sm + 4736;        // [32][36] tf32
    float* vt   = sm + 5888;        // [64][36] tf32 (V transposed)
    float* os   = sm + 2432;        // [64][68] (mode1, aliases qs/ks)

    int G  = blockIdx.x;
    int q0 = blockIdx.y * 64;
    int tid = threadIdx.x, wid = tid >> 5, lane = tid & 31;
    int lr = lane >> 2, lc = lane & 3;
    int wm = wid >> 1, wn = wid & 1;
    int mb = wm * 16;
    const float* Qg = Q + (size_t)G*NN*32;
    const float* Kg = K + (size_t)G*NN*32;
    const float* Vg = V + (size_t)G*NN*64;

    for (int idx = tid; idx < 64*32; idx += 256) {
        int r = idx >> 5, d = idx & 31;
        qs[r*36 + d] = __uint_as_float(f2tf32(scale * Qg[(size_t)(q0+r)*32 + d]));
    }

    int sr = wid*8 + lr, scg = lc;
    float m8 = -1e30f, l8 = 0.f;

    float oacc[4][4];
#pragma unroll
    for (int t = 0; t < 4; t++)
#pragma unroll
        for (int q = 0; q < 4; q++) oacc[t][q] = 0.f;

    for (int kt = 0; kt < NN; kt += 32) {
        __syncthreads();
        for (int idx = tid; idx < 32*32; idx += 256) {
            int k = idx >> 5, d = idx & 31;
            ks[k*36 + d] = __uint_as_float(f2tf32(Kg[(size_t)(kt+k)*32 + d]));
        }
        for (int idx = tid; idx < 32*64; idx += 256) {
            int k = idx >> 6, c = idx & 63;
            vt[c*36 + k] = __uint_as_float(f2tf32(Vg[(size_t)(kt+k)*64 + c]));
        }
        __syncthreads();

        float sacc[2][4];
#pragma unroll
        for (int t = 0; t < 2; t++)
#pragma unroll
            for (int q = 0; q < 4; q++) sacc[t][q] = 0.f;
#pragma unroll
        for (int k0 = 0; k0 < 32; k0 += 8) {
            unsigned a0 = __float_as_uint(qs[(mb+lr)*36   + k0+lc]);
            unsigned a1 = __float_as_uint(qs[(mb+lr+8)*36 + k0+lc]);
            unsigned a2 = __float_as_uint(qs[(mb+lr)*36   + k0+lc+4]);
            unsigned a3 = __float_as_uint(qs[(mb+lr+8)*36 + k0+lc+4]);
#pragma unroll
            for (int t = 0; t < 2; t++) {
                int n0 = 16*wn + 8*t;
                unsigned b0 = __float_as_uint(ks[(n0+lr)*36 + k0+lc]);
                unsigned b1 = __float_as_uint(ks[(n0+lr)*36 + k0+lc+4]);
                mma_tf32(sacc[t], a0, a1, a2, a3, b0, b1);
            }
        }
#pragma unroll
        for (int t = 0; t < 2; t++) {
            int col = 16*wn + 8*t + 2*lc;
            ps[(mb+lr)*36   + col]     = sacc[t][0];
            ps[(mb+lr)*36   + col + 1] = sacc[t][1];
            ps[(mb+lr+8)*36 + col]     = sacc[t][2];
            ps[(mb+lr+8)*36 + col + 1] = sacc[t][3];
        }
        __syncthreads();

        {
            float4 v0 = *(const float4*)&ps[sr*36 + 8*scg];
            float4 v1 = *(const float4*)&ps[sr*36 + 8*scg + 4];
            float tm = fmaxf(fmaxf(fmaxf(v0.x, v0.y), fmaxf(v0.z, v0.w)),
                             fmaxf(fmaxf(v1.x, v1.y), fmaxf(v1.z, v1.w)));
            tm = fmaxf(tm, __shfl_xor_sync(0xffffffffu, tm, 1));
            tm = fmaxf(tm, __shfl_xor_sync(0xffffffffu, tm, 2));
            float newm = fmaxf(m8, tm);
            float f = __expf(m8 - newm);
            m8 = newm;
            float p0 = __expf(v0.x - newm), p1 = __expf(v0.y - newm);
            float p2 = __expf(v0.z - newm), p3 = __expf(v0.w - newm);
            float p4 = __expf(v1.x - newm), p5 = __expf(v1.y - newm);
            float p6 = __expf(v1.z - newm), p7 = __expf(v1.w - newm);
            float psum = p0+p1+p2+p3+p4+p5+p6+p7;
            psum += __shfl_xor_sync(0xffffffffu, psum, 1);
            psum += __shfl_xor_sync(0xffffffffu, psum, 2);
            l8 = l8 * f + psum;
            float4 w0, w1;
            w0.x = __uint_as_float(f2tf32(p0)); w0.y = __uint_as_float(f2tf32(p1));
            w0.z = __uint_as_float(f2tf32(p2)); w0.w = __uint_as_float(f2tf32(p3));
            w1.x = __uint_as_float(f2tf32(p4)); w1.y = __uint_as_float(f2tf32(p5));
            w1.z = __uint_as_float(f2tf32(p6)); w1.w = __uint_as_float(f2tf32(p7));
            *(float4*)&ps[sr*36 + 8*scg]     = w0;
            *(float4*)&ps[sr*36 + 8*scg + 4] = w1;
            if (scg == 0) fct[sr] = f;
        }
        __syncthreads();

        {
            float f0 = fct[mb+lr], f1 = fct[mb+lr+8];
#pragma unroll
            for (int t = 0; t < 4; t++) {
                oacc[t][0] *= f0; oacc[t][1] *= f0;
                oacc[t][2] *= f1; oacc[t][3] *= f1;
            }
        }
#pragma unroll
        for (int k0 = 0; k0 < 32; k0 += 8) {
            unsigned a0 = __float_as_uint(ps[(mb+lr)*36   + k0+lc]);
            unsigned a1 = __float_as_uint(ps[(mb+lr+8)*36 + k0+lc]);
            unsigned a2 = __float_as_uint(ps[(mb+lr)*36   + k0+lc+4]);
            unsigned a3 = __float_as_uint(ps[(mb+lr+8)*36 + k0+lc+4]);
#pragma unroll
            for (int t = 0; t < 4; t++) {
                int n0 = 32*wn + 8*t;
                unsigned b0 = __float_as_uint(vt[(n0+lr)*36 + k0+lc]);
                unsigned b1 = __float_as_uint(vt[(n0+lr)*36 + k0+lc+4]);
                mma_tf32(oacc[t], a0, a1, a2, a3, b0, b1);
            }
        }
    }

    if (scg == 0) linv[sr] = 1.f / l8;
    __syncthreads();

    float i0 = linv[mb+lr], i1 = linv[mb+lr+8];
    if (mode == 0) {
#pragma unroll
        for (int t = 0; t < 4; t++) {
            int col = 32*wn + 8*t + 2*lc;
            float* o0 = &out[(size_t)(G*NN + q0 + mb + lr)*64 + col];
            float* o1 = &out[(size_t)(G*NN + q0 + mb + lr + 8)*64 + col];
            o0[0] = oacc[t][0]*i0; o0[1] = oacc[t][1]*i0;
            o1[0] = oacc[t][2]*i1; o1[1] = oacc[t][3]*i1;
        }
    } else {
#pragma unroll
        for (int t = 0; t < 4; t++) {
            int col = 32*wn + 8*t + 2*lc;
            os[(mb+lr)*68 + col]     = oacc[t][0]*i0;
            os[(mb+lr)*68 + col + 1] = oacc[t][1]*i0;
            os[(mb+lr+8)*68 + col]     = oacc[t][2]*i1;
            os[(mb+lr+8)*68 + col + 1] = oacc[t][3]*i1;
        }
        __syncthreads();
        int sIdx = G >> 4, g2 = G & 15;
        int b = g2 >> 2, seg = g2 & 3;
        int o = sIdx*LAY + layer;
        const float* gg = g_  + (size_t)o*64;
        const float* bbp = bb_ + (size_t)o*64;
#pragma unroll
        for (int rr = 0; rr < 8; rr++) {
            int r = wid*8 + rr;
            int n = q0 + r;
            float* zp = out + (size_t)(sIdx*TOK + ((b<<10)+n)*SG + seg)*HID;
            float v0 = os[r*68 + lane], v1 = os[r*68 + lane + 32];
            float ssum = v0 + v1, qq = v0*v0 + v1*v1;
#pragma unroll
            for (int off = 16; off; off >>= 1) {
                ssum += __shfl_xor_sync(0xffffffffu, ssum, off);
                qq   += __shfl_xor_sync(0xffffffffu, qq, off);
            }
            float mean = ssum * (1.f/64.f);
            float var  = qq * (1.f/64.f) - mean*mean;
            float rstd = rsqrtf(var + 1e-5f);
            zp[lane]      = (v0 - mean)*rstd*gg[lane]    + bbp[lane]    + zp[lane];
            zp[lane + 32] = (v1 - mean)*rstd*gg[lane+32] + bbp[lane+32] + zp[lane + 32];
        }
    }
}

// ---------------- mean-pool over segments + concat (both streams) ----------------
__global__ __launch_bounds__(256) void pool_kernel(const float* __restrict__ Z,
        float* __restrict__ ENC) {
    int idx = blockIdx.x * 256 + threadIdx.x;   // over 2*B*NN*64
    int s  = idx >> 18;
    int rem = idx & 262143;
    int bn = rem >> 6, h = rem & 63;
    const float* zp = Z + (size_t)(s*TOK + bn*4)*64;
    float a = 0.25f * (zp[0*64+h] + zp[1*64+h] + zp[2*64+h] + zp[3*64+h]);
    ENC[(size_t)bn*128 + s*64 + h] = a;
}

// ---------------- final cross-attention projections (in dim = 128) ----------------
__global__ __launch_bounds__(256) void fproj_kernel(const float* __restrict__ ENC,
        const float* __restrict__ wq, const float* __restrict__ wk, const float* __restrict__ wv,
        float* __restrict__ Q, float* __restrict__ K, float* __restrict__ V) {
    __shared__ float xs[64][68];
    __shared__ float ws[64][68];
    int tid = threadIdx.x;
    int r0 = blockIdx.x * 64;
    int ty = tid >> 4, tx = tid & 15;
    float acc[2][4][4];
#pragma unroll
    for (int oc = 0; oc < 2; oc++)
#pragma unroll
        for (int i = 0; i < 4; i++)
#pragma unroll
            for (int j = 0; j < 4; j++) acc[oc][i][j] = 0.f;

    for (int kc = 0; kc < 2; kc++) {
        __syncthreads();
        for (int idx = tid; idx < 64*64; idx += 256) {
            int r = idx >> 6, c = idx & 63;
            xs[r][c] = ENC[(size_t)(r0+r)*128 + kc*64 + c];
        }
        for (int oc = 0; oc < 2; oc++) {
            __syncthreads();
            for (int idx = tid; idx < 64*64; idx += 256) {
                int r = idx >> 6, c = idx & 63;
                int gc = oc*64 + r;
                int k  = kc*64 + c;
                ws[r][c] = (gc < 32) ? wq[gc*128 + k] : (gc < 64) ? wk[(gc-32)*128 + k] : wv[(gc-64)*128 + k];
            }
            __syncthreads();
#pragma unroll 4
            for (int k = 0; k < 64; k += 4) {
                float4 xv[4], wv4[4];
#pragma unroll
                for (int i = 0; i < 4; i++) xv[i] = *(const float4*)&xs[4*ty+i][k];
#pragma unroll
                for (int j = 0; j < 4; j++) wv4[j] = *(const float4*)&ws[tx+16*j][k];
#pragma unroll
                for (int i = 0; i < 4; i++)
#pragma unroll
                    for (int j = 0; j < 4; j++)
                        acc[oc][i][j] += xv[i].x*wv4[j].x + xv[i].y*wv4[j].y + xv[i].z*wv4[j].z + xv[i].w*wv4[j].w;
            }
        }
    }
#pragma unroll
    for (int oc = 0; oc < 2; oc++)
#pragma unroll
        for (int i = 0; i < 4; i++) {
            int gr = r0 + 4*ty + i;
#pragma unroll
            for (int j = 0; j < 4; j++) {
                int gc = oc*64 + tx + 16*j;
                float v = acc[oc][i][j];
                if (gc < 32)      Q[(size_t)gr*32 + gc] = v;
                else if (gc < 64) K[(size_t)gr*32 + gc - 32] = v;
                else              V[(size_t)gr*64 + gc - 64] = v;
            }
        }
}

// ---------------- host launcher ----------------
extern "C" void kernel_launch(void* const* d_in, const int* in_sizes, int n_in,
                              void* d_out, int out_size) {
    const float* traffic  = (const float*)d_in[0];
    const float* user     = (const float*)d_in[1];
    const float* patch_w  = (const float*)d_in[2];
    const float* patch_b  = (const float*)d_in[3];
    const float* mha_w    = (const float*)d_in[4];
    const float* mha_b    = (const float*)d_in[5];
    const float* out_w    = (const float*)d_in[6];
    const float* out_b    = (const float*)d_in[7];
    const float* ff1_w    = (const float*)d_in[8];
    const float* ff1_b    = (const float*)d_in[9];
    const float* ff2_w    = (const float*)d_in[10];
    const float* ff2_b    = (const float*)d_in[11];
    const float* ln1_g    = (const float*)d_in[12];
    const float* ln1_b    = (const float*)d_in[13];
    const float* ln2_g    = (const float*)d_in[14];
    const float* ln2_b    = (const float*)d_in[15];
    const float* ga_wq    = (const float*)d_in[16];
    const float* ga_wk    = (const float*)d_in[17];
    const float* ga_wv    = (const float*)d_in[18];
    const float* ga_ff1_w = (const float*)d_in[19];
    const float* ga_ff1_b = (const float*)d_in[20];
    const float* ga_ff2_w = (const float*)d_in[21];
    const float* ga_ff2_b = (const float*)d_in[22];
    const float* ga_ln1_g = (const float*)d_in[23];
    const float* ga_ln1_b = (const float*)d_in[24];
    const float* ga_ln2_g = (const float*)d_in[25];
    const float* ga_ln2_b = (const float*)d_in[26];
    const float* ca_wq    = (const float*)d_in[27];
    const float* ca_wk    = (const float*)d_in[28];
    const float* ca_wv    = (const float*)d_in[29];

    float *Z, *Qb, *Kb, *Vb, *ENC, *Q2, *K2, *V2;
    cudaGetSymbolAddress((void**)&Z,   d_Z);
    cudaGetSymbolAddress((void**)&Qb,  d_Qb);
    cudaGetSymbolAddress((void**)&Kb,  d_Kb);
    cudaGetSymbolAddress((void**)&Vb,  d_Vb);
    cudaGetSymbolAddress((void**)&ENC, d_ENC);
    cudaGetSymbolAddress((void**)&Q2,  d_Q2);
    cudaGetSymbolAddress((void**)&K2,  d_K2);
    cudaGetSymbolAddress((void**)&V2,  d_V2);

    const int MHA_SMEM = MHA_SMEM_FLOATS * 4;   // 111,616 B
    const int FF_SMEM  = FF_SMEM_FLOATS * 4;    // 204,800 B
    cudaFuncSetAttribute(mha_kernel,   cudaFuncAttributeMaxDynamicSharedMemorySize, MHA_SMEM);
    cudaFuncSetAttribute(ff_ln_kernel, cudaFuncAttributeMaxDynamicSharedMemorySize, FF_SMEM);

    const float SCALE32 = 0.17677669529663687f;   // 1/sqrt(32)

    patch_kernel<<<2*B_*NN, 256>>>(traffic, user, patch_w, patch_b, Z);
    for (int i = 0; i < LAY; i++) {
        mha_kernel<<<2*TOK/64, 256, MHA_SMEM>>>(Z, mha_w, mha_b, out_w, out_b, ln1_g, ln1_b, i);
        ff_ln_kernel<<<2*TOK/128, 256, FF_SMEM>>>(Z, ff1_w, ff1_b, ff2_w, ff2_b, ln2_g, ln2_b, i);
        ga_qkv_kernel<<<2*TOK/64, 256>>>(Z, ga_wq, ga_wk, ga_wv, Qb, Kb, Vb, i);
        attn_kernel<<<dim3(2*GRP, NN/64), 256>>>(Qb, Kb, Vb, Z, ga_ln1_g, ga_ln1_b, i, 1, SCALE32);
        ff_ln_kernel<<<2*TOK/128, 256, FF_SMEM>>>(Z, ga_ff1_w, ga_ff1_b, ga_ff2_w, ga_ff2_b, ga_ln2_g, ga_ln2_b, i);
    }
    pool_kernel<<<2*B_*NN*HID/256, 256>>>(Z, ENC);
    fproj_kernel<<<B_*NN/64, 256>>>(ENC, ca_wq, ca_wk, ca_wv, Q2, K2, V2);
    attn_kernel<<<dim3(B_, NN/64), 256>>>(Q2, K2, V2, (float*)d_out, (const float*)0, (const float*)0, 0, 0, SCALE32);
}

// round 16
// speedup vs baseline: 1.1833x; 1.0780x over previous
#include <cuda_runtime.h>
#include <math.h>

#define B_   4
#define SEQ_ 12
#define NN   1024
#define SL   3
#define SG   4
#define HID  64
#define FFD  2048
#define DKk  32
#define LAY  2
#define TOK  (B_*NN*SG)   /* 16384 per stream */
#define GRP  (B_*SG)      /* 16 per stream */

// ---------------- scratch (static device memory) ----------------
__device__ float d_Z[2*TOK*HID];          // [s][b][n][seg][h]
__device__ float d_Qb[2*GRP*NN*DKk];
__device__ float d_Kb[2*GRP*NN*DKk];
__device__ float d_Vb[2*GRP*NN*HID];
__device__ float d_ENC[B_*NN*2*HID];
__device__ float d_Q2[B_*NN*DKk];
__device__ float d_K2[B_*NN*DKk];
__device__ float d_V2[B_*NN*HID];

// ---------------- tf32 / cp.async helpers ----------------
__device__ __forceinline__ unsigned f2tf32(float x) {
    unsigned r;
    asm("cvt.rna.tf32.f32 %0, %1;" : "=r"(r) : "f"(x));
    return r;
}
__device__ __forceinline__ void mma_tf32(float* c,
        unsigned a0, unsigned a1, unsigned a2, unsigned a3,
        unsigned b0, unsigned b1) {
    asm volatile("mma.sync.aligned.m16n8k8.row.col.f32.tf32.tf32.f32 "
        "{%0,%1,%2,%3}, {%4,%5,%6,%7}, {%8,%9}, {%0,%1,%2,%3};"
        : "+f"(c[0]), "+f"(c[1]), "+f"(c[2]), "+f"(c[3])
        : "r"(a0), "r"(a1), "r"(a2), "r"(a3), "r"(b0), "r"(b1));
}
__device__ __forceinline__ void cp_async16(float* smem_dst, const float* gmem_src) {
    unsigned saddr = (unsigned)__cvta_generic_to_shared(smem_dst);
    asm volatile("cp.async.cg.shared.global [%0], [%1], 16;" :: "r"(saddr), "l"(gmem_src));
}
#define CP_COMMIT() asm volatile("cp.async.commit_group;")
#define CP_WAIT0()  asm volatile("cp.async.wait_group 0;")

// ---------------- patch embedding + positional encoding (both streams) ----------------
__global__ __launch_bounds__(256) void patch_kernel(const float* __restrict__ traffic,
                                                    const float* __restrict__ user,
                                                    const float* __restrict__ pw,
                                                    const float* __restrict__ pb,
                                                    float* __restrict__ Z) {
    int blk = blockIdx.x;                // 0..8191
    int s   = blk >> 12;
    int bn  = blk & 4095;
    int b   = bn >> 10, n = bn & 1023;
    const float* x = s ? user : traffic;
    const float* pws = pw + s*HID*SL;
    const float* pbs = pb + s*HID;
    int t   = threadIdx.x;
    int seg = t >> 6, h = t & 63;
    float acc = pbs[h];
#pragma unroll
    for (int l = 0; l < SL; l++)
        acc += pws[h*SL + l] * x[(b*SEQ_ + seg*SL + l)*NN + n];
    int he = h & ~1;
    float dv = expf(-(float)he * (9.210340371976184f / (float)HID));
    float ang = (float)seg * dv;
    acc += (h & 1) ? cosf(ang) : sinf(ang);
    Z[(size_t)(s*TOK + bn*SG + seg)*HID + h] = acc;
}

// ---------------- temporal encoder: MHA + residual + LN1; 64 tokens / block ----------------
// GEMMs (QKV, out-proj) on tf32 tensor cores; 4x4 attention core scalar.
#define MHA_SMEM_FLOATS (4352 + 4352 + 12800 + 2048 + 4352)
__global__ __launch_bounds__(256) void mha_kernel(float* __restrict__ Z,
        const float* __restrict__ mw_, const float* __restrict__ mb_,
        const float* __restrict__ ow_, const float* __restrict__ ob_,
        const float* __restrict__ g1_, const float* __restrict__ b1_, int layer) {
    extern __shared__ float sm[];
    float (*xs)[68]  = (float(*)[68])sm;
    float (*wb)[68]  = (float(*)[68])(sm + 4352);
    float (*qkv)[200]= (float(*)[200])(sm + 8704);
    float *ps        = sm + 21504;
    float (*os)[68]  = (float(*)[68])(sm + 23552);

    int tid = threadIdx.x;
    int s  = blockIdx.x >> 8;                 // 512 blocks, 256 per stream
    int o  = s*LAY + layer;
    const float* mw = mw_ + (size_t)o*192*64;
    const float* mb = mb_ + (size_t)o*192;
    const float* ow = ow_ + (size_t)o*64*64;
    const float* ob = ob_ + (size_t)o*64;
    const float* g1 = g1_ + (size_t)o*64;
    const float* b1 = b1_ + (size_t)o*64;
    size_t t0 = (size_t)blockIdx.x * 64;
    float* zb = Z + t0 * HID;

    int wid = tid >> 5, lane = tid & 31;
    int lr = lane >> 2, lc = lane & 3;
    int wm = wid >> 2, wn = wid & 3;          // warp grid 2(m) x 4(n)
    int mb2 = wm*32, nb = wn*16;

    for (int idx = tid; idx < 64*16; idx += 256) {
        int r = idx >> 4, c4 = idx & 15;
        *(float4*)&xs[r][4*c4] = *(const float4*)&zb[(size_t)r*64 + 4*c4];
    }

    // ---- QKV = X @ W^T + b  (3 chunks of 64 cols), tf32 mma ----
    for (int cc = 0; cc < 3; cc++) {
        __syncthreads();
        for (int idx = tid; idx < 64*16; idx += 256) {
            int r = idx >> 4, c4 = idx & 15;
            float4 v = *(const float4*)&mw[(size_t)(cc*64 + r)*64 + 4*c4];
            wb[r][4*c4+0] = __uint_as_float(f2tf32(v.x));
            wb[r][4*c4+1] = __uint_as_float(f2tf32(v.y));
            wb[r][4*c4+2] = __uint_as_float(f2tf32(v.z));
            wb[r][4*c4+3] = __uint_as_float(f2tf32(v.w));
        }
        __syncthreads();
        float acc[2][2][4];
#pragma unroll
        for (int j = 0; j < 2; j++) {
            int c = nb + 8*j + 2*lc;
            float bv0 = mb[cc*64 + c], bv1 = mb[cc*64 + c + 1];
#pragma unroll
            for (int t = 0; t < 2; t++) {
                acc[t][j][0] = bv0; acc[t][j][1] = bv1;
                acc[t][j][2] = bv0; acc[t][j][3] = bv1;
            }
        }
#pragma unroll
        for (int k0 = 0; k0 < 64; k0 += 8) {
            unsigned a[2][4];
#pragma unroll
            for (int t = 0; t < 2; t++) {
                int r = mb2 + 16*t + lr;
                a[t][0] = f2tf32(xs[r][k0+lc]);
                a[t][1] = f2tf32(xs[r+8][k0+lc]);
                a[t][2] = f2tf32(xs[r][k0+lc+4]);
                a[t][3] = f2tf32(xs[r+8][k0+lc+4]);
            }
#pragma unroll
            for (int j = 0; j < 2; j++) {
                unsigned b0 = __float_as_uint(wb[nb+8*j+lr][k0+lc]);
                unsigned bq = __float_as_uint(wb[nb+8*j+lr][k0+lc+4]);
#pragma unroll
                for (int t = 0; t < 2; t++)
                    mma_tf32(acc[t][j], a[t][0], a[t][1], a[t][2], a[t][3], b0, bq);
            }
        }
#pragma unroll
        for (int t = 0; t < 2; t++)
#pragma unroll
            for (int j = 0; j < 2; j++) {
                int r = mb2 + 16*t + lr, c = cc*64 + nb + 8*j + 2*lc;
                qkv[r][c]     = acc[t][j][0];
                qkv[r][c+1]   = acc[t][j][1];
                qkv[r+8][c]   = acc[t][j][2];
                qkv[r+8][c+1] = acc[t][j][3];
            }
    }
    __syncthreads();

    // ---- scores + softmax (scalar; tiny) ----
    for (int T = tid; T < 512; T += 256) {
        int g = T >> 5, h = (T >> 2) & 7, i = T & 3;
        const float* q = &qkv[g*4 + i][h*8];
        float sc[4];
#pragma unroll
        for (int j = 0; j < 4; j++) {
            const float* kk = &qkv[g*4 + j][64 + h*8];
            float a = 0.f;
#pragma unroll
            for (int d = 0; d < 8; d++) a += q[d] * kk[d];
            sc[j] = a * 0.3535533905932738f;
        }
        float m = fmaxf(fmaxf(sc[0], sc[1]), fmaxf(sc[2], sc[3]));
        float e0 = __expf(sc[0]-m), e1 = __expf(sc[1]-m), e2 = __expf(sc[2]-m), e3 = __expf(sc[3]-m);
        float inv = 1.f / (e0+e1+e2+e3);
        ps[T*4+0] = e0*inv; ps[T*4+1] = e1*inv; ps[T*4+2] = e2*inv; ps[T*4+3] = e3*inv;
    }
    __syncthreads();

    // ---- O = att @ V (scalar; tiny) ----
    {
        int ty = tid >> 4, tx = tid & 15;
#pragma unroll
        for (int i = 0; i < 4; i++) {
            int r = 4*ty + i;
            int g = r >> 2, ii = r & 3;
#pragma unroll
            for (int j = 0; j < 4; j++) {
                int c = tx + 16*j;
                int h = c >> 3;
                const float* a = ps + (((g*8 + h)*4) + ii)*4;
                os[r][c] = a[0]*qkv[g*4+0][128+c] + a[1]*qkv[g*4+1][128+c]
                         + a[2]*qkv[g*4+2][128+c] + a[3]*qkv[g*4+3][128+c];
            }
        }
    }
    __syncthreads();

    // ---- out proj + residual, tf32 mma ----
    for (int idx = tid; idx < 64*16; idx += 256) {
        int r = idx >> 4, c4 = idx & 15;
        float4 v = *(const float4*)&ow[(size_t)r*64 + 4*c4];
        wb[r][4*c4+0] = __uint_as_float(f2tf32(v.x));
        wb[r][4*c4+1] = __uint_as_float(f2tf32(v.y));
        wb[r][4*c4+2] = __uint_as_float(f2tf32(v.z));
        wb[r][4*c4+3] = __uint_as_float(f2tf32(v.w));
    }
    __syncthreads();
    {
        float acc[2][2][4];
#pragma unroll
        for (int j = 0; j < 2; j++) {
            int c = nb + 8*j + 2*lc;
            float bv0 = ob[c], bv1 = ob[c+1];
#pragma unroll
            for (int t = 0; t < 2; t++) {
                acc[t][j][0] = bv0; acc[t][j][1] = bv1;
                acc[t][j][2] = bv0; acc[t][j][3] = bv1;
            }
        }
#pragma unroll
        for (int k0 = 0; k0 < 64; k0 += 8) {
            unsigned a[2][4];
#pragma unroll
            for (int t = 0; t < 2; t++) {
                int r = mb2 + 16*t + lr;
                a[t][0] = f2tf32(os[r][k0+lc]);
                a[t][1] = f2tf32(os[r+8][k0+lc]);
                a[t][2] = f2tf32(os[r][k0+lc+4]);
                a[t][3] = f2tf32(os[r+8][k0+lc+4]);
            }
#pragma unroll
            for (int j = 0; j < 2; j++) {
                unsigned b0 = __float_as_uint(wb[nb+8*j+lr][k0+lc]);
                unsigned bq = __float_as_uint(wb[nb+8*j+lr][k0+lc+4]);
#pragma unroll
                for (int t = 0; t < 2; t++)
                    mma_tf32(acc[t][j], a[t][0], a[t][1], a[t][2], a[t][3], b0, bq);
            }
        }
        __syncthreads();
#pragma unroll
        for (int t = 0; t < 2; t++)
#pragma unroll
            for (int j = 0; j < 2; j++) {
                int r = mb2 + 16*t + lr, c = nb + 8*j + 2*lc;
                xs[r][c]     += acc[t][j][0];
                xs[r][c+1]   += acc[t][j][1];
                xs[r+8][c]   += acc[t][j][2];
                xs[r+8][c+1] += acc[t][j][3];
            }
    }
    __syncthreads();
    // ---- LN ----
    int w = tid >> 5, lane2 = tid & 31;
#pragma unroll
    for (int rr = 0; rr < 8; rr++) {
        int r = w*8 + rr;
        float v0 = xs[r][lane2], v1 = xs[r][lane2+32];
        float ssum = v0 + v1, q = v0*v0 + v1*v1;
#pragma unroll
        for (int off = 16; off; off >>= 1) { ssum += __shfl_xor_sync(0xffffffffu, ssum, off); q += __shfl_xor_sync(0xffffffffu, q, off); }
        float mean = ssum * (1.f/64.f);
        float var  = q * (1.f/64.f) - mean*mean;
        float rstd = rsqrtf(var + 1e-5f);
        zb[(size_t)r*64 + lane2]      = (v0 - mean)*rstd*g1[lane2]    + b1[lane2];
        zb[(size_t)r*64 + lane2 + 32] = (v1 - mean)*rstd*g1[lane2+32] + b1[lane2+32];
    }
}

// ---------------- fused FF + residual + LN: tf32 mma, 128 tokens/block, FF chunk 128 ----------------
// cp.async weight pipeline: w1s single-buffer (prefetched during GEMM2 while dead),
// w2s double-buffer. Weights raw fp32 in smem; tf32 cvt at fragment load.
// smem floats: xs[128][68] | hs[128][132] | w1s[128][68] | w2s[2][64][132]
#define FF_SMEM_FLOATS (8704 + 16896 + 8704 + 2*8448)
__global__ __launch_bounds__(256) void ff_ln_kernel(float* __restrict__ Z,
        const float* __restrict__ w1_, const float* __restrict__ b1_,
        const float* __restrict__ w2_, const float* __restrict__ b2_,
        const float* __restrict__ g_, const float* __restrict__ bb_, int layer) {
    extern __shared__ float sm[];
    float (*xs)[68]  = (float(*)[68])sm;
    float (*hs)[132] = (float(*)[132])(sm + 8704);
    float (*w1s)[68] = (float(*)[68])(sm + 25600);
    float* w2base    = sm + 34304;              // two [64][132] buffers

    int tid = threadIdx.x;
    int s   = blockIdx.x >> 7;           // 256 blocks, 128 per stream
    int o   = s*LAY + layer;
    const float* w1 = w1_ + (size_t)o*FFD*64;
    const float* b1 = b1_ + (size_t)o*FFD;
    const float* w2 = w2_ + (size_t)o*64*FFD;
    const float* b2 = b2_ + (size_t)o*64;
    const float* g  = g_  + (size_t)o*64;
    const float* bb = bb_ + (size_t)o*64;
    size_t t0 = (size_t)blockIdx.x * 128;

    int wid  = tid >> 5, lane = tid & 31;
    int lr = lane >> 2, lc = lane & 3;           // fragment row/col
    int wm = wid >> 2, wn = wid & 3;             // warp grid 2 x 4
    int mb = wm*64, nbh = wn*32, nbo = wn*16;

    for (int idx = tid; idx < 128*16; idx += 256) {
        int r = idx >> 4, c4 = idx & 15;
        *(float4*)&xs[r][4*c4] = *(const float4*)&Z[(t0 + r)*64 + 4*c4];
    }

    // prefetch chunk 0 weights (raw fp32)
    for (int idx = tid; idx < 2048; idx += 256) {
        int r = idx >> 4, c4 = idx & 15;
        cp_async16(&w1s[r][4*c4], &w1[(size_t)r*64 + 4*c4]);
    }
    for (int idx = tid; idx < 2048; idx += 256) {
        int r = idx >> 5, c4 = idx & 31;
        cp_async16(&w2base[r*132 + 4*c4], &w2[(size_t)r*FFD + 4*c4]);
    }
    CP_COMMIT();
    CP_WAIT0();
    __syncthreads();

    float oacc[4][2][4];
#pragma unroll
    for (int t = 0; t < 4; t++)
#pragma unroll
        for (int j = 0; j < 2; j++)
#pragma unroll
            for (int q = 0; q < 4; q++) oacc[t][j][q] = 0.f;

    for (int ci = 0; ci < FFD/128; ci++) {
        int fc = ci * 128;
        float* w2cur = w2base + (ci & 1) * 8448;

        // ---- H[128][128] = relu(X @ W1c^T + b1c), tf32 mma ----
        float hacc[4][4][4];
#pragma unroll
        for (int t = 0; t < 4; t++)
#pragma unroll
            for (int j = 0; j < 4; j++)
#pragma unroll
                for (int q = 0; q < 4; q++) hacc[t][j][q] = 0.f;

#pragma unroll
        for (int k0 = 0; k0 < 64; k0 += 8) {
            unsigned a[4][4];
#pragma unroll
            for (int t = 0; t < 4; t++) {
                int r = mb + 16*t + lr;
                a[t][0] = f2tf32(xs[r][k0+lc]);
                a[t][1] = f2tf32(xs[r+8][k0+lc]);
                a[t][2] = f2tf32(xs[r][k0+lc+4]);
                a[t][3] = f2tf32(xs[r+8][k0+lc+4]);
            }
#pragma unroll
            for (int j = 0; j < 4; j++) {
                unsigned b0 = f2tf32(w1s[nbh+8*j+lr][k0+lc]);
                unsigned bq = f2tf32(w1s[nbh+8*j+lr][k0+lc+4]);
#pragma unroll
                for (int t = 0; t < 4; t++)
                    mma_tf32(hacc[t][j], a[t][0], a[t][1], a[t][2], a[t][3], b0, bq);
            }
        }
#pragma unroll
        for (int j = 0; j < 4; j++) {
            int c = nbh + 8*j + 2*lc;
            float bv0 = b1[fc + c], bv1 = b1[fc + c + 1];
#pragma unroll
            for (int t = 0; t < 4; t++) {
                int r = mb + 16*t + lr;
                hs[r][c]     = __uint_as_float(f2tf32(fmaxf(hacc[t][j][0] + bv0, 0.f)));
                hs[r][c+1]   = __uint_as_float(f2tf32(fmaxf(hacc[t][j][1] + bv1, 0.f)));
                hs[r+8][c]   = __uint_as_float(f2tf32(fmaxf(hacc[t][j][2] + bv0, 0.f)));
                hs[r+8][c+1] = __uint_as_float(f2tf32(fmaxf(hacc[t][j][3] + bv1, 0.f)));
            }
        }
        __syncthreads();   // hs ready; all warps past GEMM1 (w1s dead)

        // prefetch next chunk's weights while GEMM2 runs
        if (ci + 1 < FFD/128) {
            int fcn = fc + 128;
            float* w2nxt = w2base + ((ci + 1) & 1) * 8448;
            for (int idx = tid; idx < 2048; idx += 256) {
                int r = idx >> 4, c4 = idx & 15;
                cp_async16(&w1s[r][4*c4], &w1[(size_t)(fcn + r)*64 + 4*c4]);
            }
            for (int idx = tid; idx < 2048; idx += 256) {
                int r = idx >> 5, c4 = idx & 31;
                cp_async16(&w2nxt[r*132 + 4*c4], &w2[(size_t)r*FFD + fcn + 4*c4]);
            }
            CP_COMMIT();
        }

        // ---- O[128][64] += H @ W2c^T, tf32 mma ----
#pragma unroll
        for (int k0 = 0; k0 < 128; k0 += 8) {
            unsigned a[4][4];
#pragma unroll
            for (int t = 0; t < 4; t++) {
                int r = mb + 16*t + lr;
                a[t][0] = __float_as_uint(hs[r][k0+lc]);
                a[t][1] = __float_as_uint(hs[r+8][k0+lc]);
                a[t][2] = __float_as_uint(hs[r][k0+lc+4]);
                a[t][3] = __float_as_uint(hs[r+8][k0+lc+4]);
            }
#pragma unroll
            for (int j = 0; j < 2; j++) {
                unsigned b0 = f2tf32(w2cur[(nbo+8*j+lr)*132 + k0+lc]);
                unsigned bq = f2tf32(w2cur[(nbo+8*j+lr)*132 + k0+lc+4]);
#pragma unroll
                for (int t = 0; t < 4; t++)
                    mma_tf32(oacc[t][j], a[t][0], a[t][1], a[t][2], a[t][3], b0, bq);
            }
        }
        CP_WAIT0();        // next weights landed
        __syncthreads();   // hs free for overwrite; staged weights visible
    }

    // residual: each (r,c) has exactly one owner thread
#pragma unroll
    for (int j = 0; j < 2; j++) {
        int c = nbo + 8*j + 2*lc;
        float bv0 = b2[c], bv1 = b2[c+1];
#pragma unroll
        for (int t = 0; t < 4; t++) {
            int r = mb + 16*t + lr;
            xs[r][c]     += oacc[t][j][0] + bv0;
            xs[r][c+1]   += oacc[t][j][1] + bv1;
            xs[r+8][c]   += oacc[t][j][2] + bv0;
            xs[r+8][c+1] += oacc[t][j][3] + bv1;
        }
    }
    __syncthreads();
    int w = tid >> 5, lane2 = tid & 31;
#pragma unroll
    for (int rr = 0; rr < 16; rr++) {
        int r = w*16 + rr;
        float v0 = xs[r][lane2], v1 = xs[r][lane2+32];
        float ssum = v0 + v1, q = v0*v0 + v1*v1;
#pragma unroll
        for (int off = 16; off; off >>= 1) { ssum += __shfl_xor_sync(0xffffffffu, ssum, off); q += __shfl_xor_sync(0xffffffffu, q, off); }
        float mean = ssum * (1.f/64.f);
        float var  = q * (1.f/64.f) - mean*mean;
        float rstd = rsqrtf(var + 1e-5f);
        Z[(t0+r)*64 + lane2]      = (v0 - mean)*rstd*g[lane2]    + bb[lane2];
        Z[(t0+r)*64 + lane2 + 32] = (v1 - mean)*rstd*g[lane2+32] + bb[lane2+32];
    }
}

// ---------------- graph-attention QKV projection: tf32 mma, 64 rows/block ----------------
__global__ __launch_bounds__(256) void ga_qkv_kernel(const float* __restrict__ Z,
        const float* __restrict__ wq_, const float* __restrict__ wk_, const float* __restrict__ wv_,
        float* __restrict__ Q, float* __restrict__ K, float* __restrict__ V, int layer) {
    __shared__ float xs[64][68];   // tf32
    __shared__ float ws[64][68];   // tf32
    int tid = threadIdx.x;
    int r0 = blockIdx.x * 64;
    int s  = r0 >> 14;
    int o  = s*LAY + layer;
    const float* wq = wq_ + (size_t)o*DKk*64;
    const float* wk = wk_ + (size_t)o*DKk*64;
    const float* wv = wv_ + (size_t)o*64*64;

    int wid = tid >> 5, lane = tid & 31;
    int lr = lane >> 2, lc = lane & 3;
    int wm = wid >> 2, wn = wid & 3;          // 2(m) x 4(n)
    int mb = wm*32, nb = wn*16;

    for (int idx = tid; idx < 64*64; idx += 256) {
        int r = idx >> 6, c = idx & 63;
        int gr = r0 + r;
        int q  = gr & 16383;
        int g2 = q >> 10, n = q & 1023;
        int b = g2 >> 2, seg = g2 & 3;
        xs[r][c] = __uint_as_float(f2tf32(Z[(size_t)(s*TOK + ((b<<10)+n)*SG + seg)*HID + c]));
    }
    for (int chunk = 0; chunk < 2; chunk++) {
        __syncthreads();
        for (int idx = tid; idx < 64*64; idx += 256) {
            int r = idx >> 6, c = idx & 63;
            float v = (chunk == 0) ? (r < 32 ? wq[r*64 + c] : wk[(r-32)*64 + c]) : wv[r*64 + c];
            ws[r][c] = __uint_as_float(f2tf32(v));
        }
        __syncthreads();
        float acc[2][2][4];
#pragma unroll
        for (int t = 0; t < 2; t++)
#pragma unroll
            for (int j = 0; j < 2; j++)
#pragma unroll
                for (int q = 0; q < 4; q++) acc[t][j][q] = 0.f;
#pragma unroll
        for (int k0 = 0; k0 < 64; k0 += 8) {
            unsigned a[2][4];
#pragma unroll
            for (int t = 0; t < 2; t++) {
                int r = mb + 16*t + lr;
                a[t][0] = __float_as_uint(xs[r][k0+lc]);
                a[t][1] = __float_as_uint(xs[r+8][k0+lc]);
                a[t][2] = __float_as_uint(xs[r][k0+lc+4]);
                a[t][3] = __float_as_uint(xs[r+8][k0+lc+4]);
            }
#pragma unroll
            for (int j = 0; j < 2; j++) {
                unsigned b0 = __float_as_uint(ws[nb+8*j+lr][k0+lc]);
                unsigned bq = __float_as_uint(ws[nb+8*j+lr][k0+lc+4]);
#pragma unroll
                for (int t = 0; t < 2; t++)
                    mma_tf32(acc[t][j], a[t][0], a[t][1], a[t][2], a[t][3], b0, bq);
            }
        }
#pragma unroll
        for (int t = 0; t < 2; t++)
#pragma unroll
            for (int j = 0; j < 2; j++) {
                int c = nb + 8*j + 2*lc;
                int gr0 = r0 + mb + 16*t + lr;
#pragma unroll
                for (int half = 0; half < 2; half++) {
                    int gr = gr0 + 8*half;
                    float v0 = acc[t][j][2*half], v1 = acc[t][j][2*half+1];
                    if (chunk == 0) {
                        if (c < 32) { Q[(size_t)gr*32 + c] = v0;      Q[(size_t)gr*32 + c + 1] = v1; }
                        else        { K[(size_t)gr*32 + c - 32] = v0; K[(size_t)gr*32 + c - 31] = v1; }
                    } else        { V[(size_t)gr*64 + c] = v0;      V[(size_t)gr*64 + c + 1] = v1; }
                }
            }
    }
}

// ---------------- attention: tf32 tensor-core flash attention; dk=32, dv=64, N=1024/group ----------------
// Register-prefetched K/V tiles: next tile's LDGs issue before compute, land during MMA+softmax.
// mode 0: plain write to out[(G*NN+q)*64+c] ; mode 1: GA epilogue — Z = LN(att)*g+b + Z
__global__ __launch_bounds__(256) void attn_kernel(const float* __restrict__ Q,
        const float* __restrict__ K, const float* __restrict__ V,
        float* __restrict__ out, const float* __restrict__ g_, const float* __restrict__ bb_,
        int layer, int mode, float scale) {
    __shared__ float sm[8192];
    float* ps   = sm;               // [64][36]
    float* fct  = sm + 2304;        // [64]
    float* linv = sm + 2368;        // [64]
    float* qs   = sm + 2432;        // [64][36] tf32
    float* ks   = sm + 4736;        // [32][36] tf32
    float* vt   = sm + 5888;        // [64][36] tf32 (V transposed)
    float* os   = sm + 2432;        // [64][68] (mode1, aliases qs/ks)

    int G  = blockIdx.x;
    int q0 = blockIdx.y * 64;
    int tid = threadIdx.x, wid = tid >> 5, lane = tid & 31;
    int lr = lane >> 2, lc = lane & 3;
    int wm = wid >> 1, wn = wid & 1;
    int mb = wm * 16;
    const float* Qg = Q + (size_t)G*NN*32;
    const float* Kg = K + (size_t)G*NN*32;
    const float* Vg = V + (size_t)G*NN*64;

    for (int idx = tid; idx < 64*32; idx += 256) {
        int r = idx >> 5, d = idx & 31;
        qs[r*36 + d] = __uint_as_float(f2tf32(scale * Qg[(size_t)(q0+r)*32 + d]));
    }

    int sr = wid*8 + lr, scg = lc;
    float m8 = -1e30f, l8 = 0.f;

    float oacc[4][4];
#pragma unroll
    for (int t = 0; t < 4; t++)
#pragma unroll
        for (int q = 0; q < 4; q++) oacc[t][q] = 0.f;

    // register prefetch of tile 0 (K: 4 floats/thread, V: 8 floats/thread)
    float kpre[4], vpre[8];
#pragma unroll
    for (int i = 0; i < 4; i++) kpre[i] = Kg[tid + i*256];
#pragma unroll
    for (int i = 0; i < 8; i++) vpre[i] = Vg[tid + i*256];

    for (int kt = 0; kt < NN; kt += 32) {
        __syncthreads();   // prior iteration's smem reads done
        // store prefetched tile (cvt to tf32)
#pragma unroll
        for (int i = 0; i < 4; i++) {
            int idx = tid + i*256;
            ks[(idx >> 5)*36 + (idx & 31)] = __uint_as_float(f2tf32(kpre[i]));
        }
#pragma unroll
        for (int i = 0; i < 8; i++) {
            int idx = tid + i*256;
            vt[(idx & 63)*36 + (idx >> 6)] = __uint_as_float(f2tf32(vpre[i]));
        }
        __syncthreads();
        // issue next tile's loads — they land during the compute below
        if (kt + 32 < NN) {
#pragma unroll
            for (int i = 0; i < 4; i++) kpre[i] = Kg[(size_t)(kt+32)*32 + tid + i*256];
#pragma unroll
            for (int i = 0; i < 8; i++) vpre[i] = Vg[(size_t)(kt+32)*64 + tid + i*256];
        }

        float sacc[2][4];
#pragma unroll
        for (int t = 0; t < 2; t++)
#pragma unroll
            for (int q = 0; q < 4; q++) sacc[t][q] = 0.f;
#pragma unroll
        for (int k0 = 0; k0 < 32; k0 += 8) {
            unsigned a0 = __float_as_uint(qs[(mb+lr)*36   + k0+lc]);
            unsigned a1 = __float_as_uint(qs[(mb+lr+8)*36 + k0+lc]);
            unsigned a2 = __float_as_uint(qs[(mb+lr)*36   + k0+lc+4]);
            unsigned a3 = __float_as_uint(qs[(mb+lr+8)*36 + k0+lc+4]);
#pragma unroll
            for (int t = 0; t < 2; t++) {
                int n0 = 16*wn + 8*t;
                unsigned b0 = __float_as_uint(ks[(n0+lr)*36 + k0+lc]);
                unsigned b1 = __float_as_uint(ks[(n0+lr)*36 + k0+lc+4]);
                mma_tf32(sacc[t], a0, a1, a2, a3, b0, b1);
            }
        }
#pragma unroll
        for (int t = 0; t < 2; t++) {
            int col = 16*wn + 8*t + 2*lc;
            ps[(mb+lr)*36   + col]     = sacc[t][0];
            ps[(mb+lr)*36   + col + 1] = sacc[t][1];
            ps[(mb+lr+8)*36 + col]     = sacc[t][2];
            ps[(mb+lr+8)*36 + col + 1] = sacc[t][3];
        }
        __syncthreads();

        {
            float4 v0 = *(const float4*)&ps[sr*36 + 8*scg];
            float4 v1 = *(const float4*)&ps[sr*36 + 8*scg + 4];
            float tm = fmaxf(fmaxf(fmaxf(v0.x, v0.y), fmaxf(v0.z, v0.w)),
                             fmaxf(fmaxf(v1.x, v1.y), fmaxf(v1.z, v1.w)));
            tm = fmaxf(tm, __shfl_xor_sync(0xffffffffu, tm, 1));
            tm = fmaxf(tm, __shfl_xor_sync(0xffffffffu, tm, 2));
            float newm = fmaxf(m8, tm);
            float f = __expf(m8 - newm);
            m8 = newm;
            float p0 = __expf(v0.x - newm), p1 = __expf(v0.y - newm);
            float p2 = __expf(v0.z - newm), p3 = __expf(v0.w - newm);
            float p4 = __expf(v1.x - newm), p5 = __expf(v1.y - newm);
            float p6 = __expf(v1.z - newm), p7 = __expf(v1.w - newm);
            float psum = p0+p1+p2+p3+p4+p5+p6+p7;
            psum += __shfl_xor_sync(0xffffffffu, psum, 1);
            psum += __shfl_xor_sync(0xffffffffu, psum, 2);
            l8 = l8 * f + psum;
            float4 w0, w1;
            w0.x = __uint_as_float(f2tf32(p0)); w0.y = __uint_as_float(f2tf32(p1));
            w0.z = __uint_as_float(f2tf32(p2)); w0.w = __uint_as_float(f2tf32(p3));
            w1.x = __uint_as_float(f2tf32(p4)); w1.y = __uint_as_float(f2tf32(p5));
            w1.z = __uint_as_float(f2tf32(p6)); w1.w = __uint_as_float(f2tf32(p7));
            *(float4*)&ps[sr*36 + 8*scg]     = w0;
            *(float4*)&ps[sr*36 + 8*scg + 4] = w1;
            if (scg == 0) fct[sr] = f;
        }
        __syncthreads();

        {
            float f0 = fct[mb+lr], f1 = fct[mb+lr+8];
#pragma unroll
            for (int t = 0; t < 4; t++) {
                oacc[t][0] *= f0; oacc[t][1] *= f0;
                oacc[t][2] *= f1; oacc[t][3] *= f1;
            }
        }
#pragma unroll
        for (int k0 = 0; k0 < 32; k0 += 8) {
            unsigned a0 = __float_as_uint(ps[(mb+lr)*36   + k0+lc]);
            unsigned a1 = __float_as_uint(ps[(mb+lr+8)*36 + k0+lc]);
            unsigned a2 = __float_as_uint(ps[(mb+lr)*36   + k0+lc+4]);
            unsigned a3 = __float_as_uint(ps[(mb+lr+8)*36 + k0+lc+4]);
#pragma unroll
            for (int t = 0; t < 4; t++) {
                int n0 = 32*wn + 8*t;
                unsigned b0 = __float_as_uint(vt[(n0+lr)*36 + k0+lc]);
                unsigned b1 = __float_as_uint(vt[(n0+lr)*36 + k0+lc+4]);
                mma_tf32(oacc[t], a0, a1, a2, a3, b0, b1);
            }
        }
    }

    if (scg == 0) linv[sr] = 1.f / l8;
    __syncthreads();

    float i0 = linv[mb+lr], i1 = linv[mb+lr+8];
    if (mode == 0) {
#pragma unroll
        for (int t = 0; t < 4; t++) {
            int col = 32*wn + 8*t + 2*lc;
            float* o0 = &out[(size_t)(G*NN + q0 + mb + lr)*64 + col];
            float* o1 = &out[(size_t)(G*NN + q0 + mb + lr + 8)*64 + col];
            o0[0] = oacc[t][0]*i0; o0[1] = oacc[t][1]*i0;
            o1[0] = oacc[t][2]*i1; o1[1] = oacc[t][3]*i1;
        }
    } else {
#pragma unroll
        for (int t = 0; t < 4; t++) {
            int col = 32*wn + 8*t + 2*lc;
            os[(mb+lr)*68 + col]     = oacc[t][0]*i0;
            os[(mb+lr)*68 + col + 1] = oacc[t][1]*i0;
            os[(mb+lr+8)*68 + col]     = oacc[t][2]*i1;
            os[(mb+lr+8)*68 + col + 1] = oacc[t][3]*i1;
        }
        __syncthreads();
        int sIdx = G >> 4, g2 = G & 15;
        int b = g2 >> 2, seg = g2 & 3;
        int o = sIdx*LAY + layer;
        const float* gg = g_  + (size_t)o*64;
        const float* bbp = bb_ + (size_t)o*64;
#pragma unroll
        for (int rr = 0; rr < 8; rr++) {
            int r = wid*8 + rr;
            int n = q0 + r;
            float* zp = out + (size_t)(sIdx*TOK + ((b<<10)+n)*SG + seg)*HID;
            float v0 = os[r*68 + lane], v1 = os[r*68 + lane + 32];
            float ssum = v0 + v1, qq = v0*v0 + v1*v1;
#pragma unroll
            for (int off = 16; off; off >>= 1) {
                ssum += __shfl_xor_sync(0xffffffffu, ssum, off);
                qq   += __shfl_xor_sync(0xffffffffu, qq, off);
            }
            float mean = ssum * (1.f/64.f);
            float var  = qq * (1.f/64.f) - mean*mean;
            float rstd = rsqrtf(var + 1e-5f);
            zp[lane]      = (v0 - mean)*rstd*gg[lane]    + bbp[lane]    + zp[lane];
            zp[lane + 32] = (v1 - mean)*rstd*gg[lane+32] + bbp[lane+32] + zp[lane + 32];
        }
    }
}

// ---------------- mean-pool over segments + concat (both streams) ----------------
__global__ __launch_bounds__(256) void pool_kernel(const float* __restrict__ Z,
        float* __restrict__ ENC) {
    int idx = blockIdx.x * 256 + threadIdx.x;   // over 2*B*NN*64
    int s  = idx >> 18;
    int rem = idx & 262143;
    int bn = rem >> 6, h = rem & 63;
    const float* zp = Z + (size_t)(s*TOK + bn*4)*64;
    float a = 0.25f * (zp[0*64+h] + zp[1*64+h] + zp[2*64+h] + zp[3*64+h]);
    ENC[(size_t)bn*128 + s*64 + h] = a;
}

// ---------------- final cross-attention projections (in dim = 128) ----------------
__global__ __launch_bounds__(256) void fproj_kernel(const float* __restrict__ ENC,
        const float* __restrict__ wq, const float* __restrict__ wk, const float* __restrict__ wv,
        float* __restrict__ Q, float* __restrict__ K, float* __restrict__ V) {
    __shared__ float xs[64][68];
    __shared__ float ws[64][68];
    int tid = threadIdx.x;
    int r0 = blockIdx.x * 64;
    int ty = tid >> 4, tx = tid & 15;
    float acc[2][4][4];
#pragma unroll
    for (int oc = 0; oc < 2; oc++)
#pragma unroll
        for (int i = 0; i < 4; i++)
#pragma unroll
            for (int j = 0; j < 4; j++) acc[oc][i][j] = 0.f;

    for (int kc = 0; kc < 2; kc++) {
        __syncthreads();
        for (int idx = tid; idx < 64*64; idx += 256) {
            int r = idx >> 6, c = idx & 63;
            xs[r][c] = ENC[(size_t)(r0+r)*128 + kc*64 + c];
        }
        for (int oc = 0; oc < 2; oc++) {
            __syncthreads();
            for (int idx = tid; idx < 64*64; idx += 256) {
                int r = idx >> 6, c = idx & 63;
                int gc = oc*64 + r;
                int k  = kc*64 + c;
                ws[r][c] = (gc < 32) ? wq[gc*128 + k] : (gc < 64) ? wk[(gc-32)*128 + k] : wv[(gc-64)*128 + k];
            }
            __syncthreads();
#pragma unroll 4
            for (int k = 0; k < 64; k += 4) {
                float4 xv[4], wv4[4];
#pragma unroll
                for (int i = 0; i < 4; i++) xv[i] = *(const float4*)&xs[4*ty+i][k];
#pragma unroll
                for (int j = 0; j < 4; j++) wv4[j] = *(const float4*)&ws[tx+16*j][k];
#pragma unroll
                for (int i = 0; i < 4; i++)
#pragma unroll
                    for (int j = 0; j < 4; j++)
                        acc[oc][i][j] += xv[i].x*wv4[j].x + xv[i].y*wv4[j].y + xv[i].z*wv4[j].z + xv[i].w*wv4[j].w;
            }
        }
    }
#pragma unroll
    for (int oc = 0; oc < 2; oc++)
#pragma unroll
        for (int i = 0; i < 4; i++) {
            int gr = r0 + 4*ty + i;
#pragma unroll
            for (int j = 0; j < 4; j++) {
                int gc = oc*64 + tx + 16*j;
                float v = acc[oc][i][j];
                if (gc < 32)      Q[(size_t)gr*32 + gc] = v;
                else if (gc < 64) K[(size_t)gr*32 + gc - 32] = v;
                else              V[(size_t)gr*64 + gc - 64] = v;
            }
        }
}

// ---------------- host launcher ----------------
extern "C" void kernel_launch(void* const* d_in, const int* in_sizes, int n_in,
                              void* d_out, int out_size) {
    const float* traffic  = (const float*)d_in[0];
    const float* user     = (const float*)d_in[1];
    const float* patch_w  = (const float*)d_in[2];
    const float* patch_b  = (const float*)d_in[3];
    const float* mha_w    = (const float*)d_in[4];
    const float* mha_b    = (const float*)d_in[5];
    const float* out_w    = (const float*)d_in[6];
    const float* out_b    = (const float*)d_in[7];
    const float* ff1_w    = (const float*)d_in[8];
    const float* ff1_b    = (const float*)d_in[9];
    const float* ff2_w    = (const float*)d_in[10];
    const float* ff2_b    = (const float*)d_in[11];
    const float* ln1_g    = (const float*)d_in[12];
    const float* ln1_b    = (const float*)d_in[13];
    const float* ln2_g    = (const float*)d_in[14];
    const float* ln2_b    = (const float*)d_in[15];
    const float* ga_wq    = (const float*)d_in[16];
    const float* ga_wk    = (const float*)d_in[17];
    const float* ga_wv    = (const float*)d_in[18];
    const float* ga_ff1_w = (const float*)d_in[19];
    const float* ga_ff1_b = (const float*)d_in[20];
    const float* ga_ff2_w = (const float*)d_in[21];
    const float* ga_ff2_b = (const float*)d_in[22];
    const float* ga_ln1_g = (const float*)d_in[23];
    const float* ga_ln1_b = (const float*)d_in[24];
    const float* ga_ln2_g = (const float*)d_in[25];
    const float* ga_ln2_b = (const float*)d_in[26];
    const float* ca_wq    = (const float*)d_in[27];
    const float* ca_wk    = (const float*)d_in[28];
    const float* ca_wv    = (const float*)d_in[29];

    float *Z, *Qb, *Kb, *Vb, *ENC, *Q2, *K2, *V2;
    cudaGetSymbolAddress((void**)&Z,   d_Z);
    cudaGetSymbolAddress((void**)&Qb,  d_Qb);
    cudaGetSymbolAddress((void**)&Kb,  d_Kb);
    cudaGetSymbolAddress((void**)&Vb,  d_Vb);
    cudaGetSymbolAddress((void**)&ENC, d_ENC);
    cudaGetSymbolAddress((void**)&Q2,  d_Q2);
    cudaGetSymbolAddress((void**)&K2,  d_K2);
    cudaGetSymbolAddress((void**)&V2,  d_V2);

    const int MHA_SMEM = MHA_SMEM_FLOATS * 4;   // 111,616 B
    const int FF_SMEM  = FF_SMEM_FLOATS * 4;    // 204,800 B
    cudaFuncSetAttribute(mha_kernel,   cudaFuncAttributeMaxDynamicSharedMemorySize, MHA_SMEM);
    cudaFuncSetAttribute(ff_ln_kernel, cudaFuncAttributeMaxDynamicSharedMemorySize, FF_SMEM);

    const float SCALE32 = 0.17677669529663687f;   // 1/sqrt(32)

    patch_kernel<<<2*B_*NN, 256>>>(traffic, user, patch_w, patch_b, Z);
    for (int i = 0; i < LAY; i++) {
        mha_kernel<<<2*TOK/64, 256, MHA_SMEM>>>(Z, mha_w, mha_b, out_w, out_b, ln1_g, ln1_b, i);
        ff_ln_kernel<<<2*TOK/128, 256, FF_SMEM>>>(Z, ff1_w, ff1_b, ff2_w, ff2_b, ln2_g, ln2_b, i);
        ga_qkv_kernel<<<2*TOK/64, 256>>>(Z, ga_wq, ga_wk, ga_wv, Qb, Kb, Vb, i);
        attn_kernel<<<dim3(2*GRP, NN/64), 256>>>(Qb, Kb, Vb, Z, ga_ln1_g, ga_ln1_b, i, 1, SCALE32);
        ff_ln_kernel<<<2*TOK/128, 256, FF_SMEM>>>(Z, ga_ff1_w, ga_ff1_b, ga_ff2_w, ga_ff2_b, ga_ln2_g, ga_ln2_b, i);
    }
    pool_kernel<<<2*B_*NN*HID/256, 256>>>(Z, ENC);
    fproj_kernel<<<B_*NN/64, 256>>>(ENC, ca_wq, ca_wk, ca_wv, Q2, K2, V2);
    attn_kernel<<<dim3(B_, NN/64), 256>>>(Q2, K2, V2, (float*)d_out, (const float*)0, (const float*)0, 0, 0, SCALE32);
}